// round 1
// baseline (speedup 1.0000x reference)
#include <cuda_runtime.h>
#include <math.h>

#define B 64
#define UNITS 512
#define EMB 256
#define NSENT 32
#define NWORD 50
#define VOCAB 50000
#define OOV 100
#define EXT (VOCAB + OOV)

// output offsets
#define DEC_OFF   0
#define GEN_OFF   (B*UNITS)
#define COPY_OFF  (GEN_OFF + B*EXT)
#define PGEN_OFF  (COPY_OFF + B*EXT)

// ---------------- scratch ----------------
__device__ float g_xm[B * 3 * UNITS];
__device__ float g_hm[B * 3 * UNITS];
__device__ float g_q[B * UNITS];
__device__ float g_qw[B * UNITS];
__device__ float g_alpha[B * NSENT];
__device__ float g_xcat[B * 2 * UNITS];   // [context | dec]
__device__ float g_beta[B * NSENT * NWORD];
__device__ float g_hidden[B * (UNITS/2)];
__device__ float g_stats[B * 2];          // max, sum

// ---------------- generic GEMM: C[64,N] = A[64,K] @ B[K,N] (+bias)(+act) ----------------
// block tile: M=64, N=128, Kchunk=32. 256 threads, each 4x8 micro-tile.
__global__ __launch_bounds__(256) void gemm64_kernel(
    const float* __restrict__ A, int lda,
    const float* __restrict__ Bm, int ldb,
    const float* __restrict__ bias,
    float* __restrict__ C, int ldc,
    int K, int Nreal, int act)
{
    __shared__ float As[32 * 68];    // [k][m], padded
    __shared__ float Bs[32 * 128];   // [k][n]

    int tid = threadIdx.x;
    int tm = tid >> 4;     // 0..15 -> m = tm*4 + jm
    int tc = tid & 15;     // 0..15 -> n = n0 + tc*8 + jn
    int n0 = blockIdx.x * 128;

    float acc[4][8];
#pragma unroll
    for (int i = 0; i < 4; i++)
#pragma unroll
        for (int j = 0; j < 8; j++) acc[i][j] = 0.f;

    for (int k0 = 0; k0 < K; k0 += 32) {
        // load A tile transposed: As[kk][m] = A[m*lda + k0+kk]
#pragma unroll
        for (int i = 0; i < 8; i++) {
            int idx = i * 256 + tid;       // 0..2047
            int m  = idx >> 5;
            int kk = idx & 31;
            As[kk * 68 + m] = A[(size_t)m * lda + k0 + kk];
        }
        // load B tile: Bs[kk][c]
#pragma unroll
        for (int i = 0; i < 4; i++) {
            int v  = i * 256 + tid;        // 0..1023
            int kk = v >> 5;
            int c  = (v & 31) * 4;
            int n  = n0 + c;
            float4 val;
            if (n < Nreal) val = *(const float4*)(Bm + (size_t)(k0 + kk) * ldb + n);
            else val = make_float4(0.f, 0.f, 0.f, 0.f);
            *(float4*)(&Bs[kk * 128 + c]) = val;
        }
        __syncthreads();
#pragma unroll
        for (int k = 0; k < 32; k++) {
            float4 a  = *(float4*)(&As[k * 68 + tm * 4]);
            float4 b0 = *(float4*)(&Bs[k * 128 + tc * 8]);
            float4 b1 = *(float4*)(&Bs[k * 128 + tc * 8 + 4]);
            float av[4] = {a.x, a.y, a.z, a.w};
            float bv[8] = {b0.x, b0.y, b0.z, b0.w, b1.x, b1.y, b1.z, b1.w};
#pragma unroll
            for (int jm = 0; jm < 4; jm++)
#pragma unroll
                for (int jn = 0; jn < 8; jn++)
                    acc[jm][jn] += av[jm] * bv[jn];
        }
        __syncthreads();
    }

#pragma unroll
    for (int jm = 0; jm < 4; jm++) {
        int m = tm * 4 + jm;
#pragma unroll
        for (int jn = 0; jn < 8; jn++) {
            int n = n0 + tc * 8 + jn;
            if (n < Nreal) {
                float v = acc[jm][jn];
                if (bias) v += bias[n];
                if (act == 1) v = tanhf(v);
                C[(size_t)m * ldc + n] = v;
            }
        }
    }
}

// ---------------- GRU gate (elementwise) ----------------
__global__ void gru_gate_kernel(const float* __restrict__ hprev,
                                float* __restrict__ out /*d_out*/)
{
    int idx = blockIdx.x * blockDim.x + threadIdx.x;   // 64*512
    if (idx >= B * UNITS) return;
    int b = idx >> 9;
    int u = idx & 511;
    const float* xm = g_xm + b * (3 * UNITS);
    const float* hm = g_hm + b * (3 * UNITS);
    float z  = 1.f / (1.f + expf(-(xm[u] + hm[u])));
    float r  = 1.f / (1.f + expf(-(xm[UNITS + u] + hm[UNITS + u])));
    float hc = tanhf(xm[2 * UNITS + u] + r * hm[2 * UNITS + u]);
    float h  = hprev[idx];
    float hn = z * h + (1.f - z) * hc;
    out[DEC_OFF + idx] = hn;
    g_xcat[b * (2 * UNITS) + UNITS + u] = hn;   // second half of concat
}

// ---------------- sentence attention: scores/softmax/context ----------------
__global__ __launch_bounds__(256) void attn_sent_kernel(
    const float* __restrict__ encS)     // [B, NSENT, UNITS]
{
    __shared__ float q_s[UNITS];
    __shared__ float sc_s[NSENT];
    __shared__ float alpha_s[NSENT];

    int b = blockIdx.x;
    int tid = threadIdx.x;
    int warp = tid >> 5, lane = tid & 31;

    for (int u = tid; u < UNITS; u += 256) q_s[u] = g_q[b * UNITS + u];
    __syncthreads();

    // 8 warps x 4 sentences
#pragma unroll
    for (int i = 0; i < 4; i++) {
        int s = warp * 4 + i;
        const float4* row = (const float4*)(encS + ((size_t)(b * NSENT + s)) * UNITS);
        const float4* qv  = (const float4*)q_s;
        float acc = 0.f;
#pragma unroll
        for (int t = 0; t < 4; t++) {
            float4 e = row[lane + t * 32];
            float4 qq = qv[lane + t * 32];
            acc += e.x * qq.x + e.y * qq.y + e.z * qq.z + e.w * qq.w;
        }
#pragma unroll
        for (int o = 16; o > 0; o >>= 1) acc += __shfl_down_sync(0xffffffffu, acc, o);
        if (lane == 0) sc_s[s] = acc;
    }
    __syncthreads();

    if (warp == 0) {
        float x = sc_s[lane];
        float m = x;
#pragma unroll
        for (int o = 16; o > 0; o >>= 1) m = fmaxf(m, __shfl_xor_sync(0xffffffffu, m, o));
        float e = expf(x - m);
        float s = e;
#pragma unroll
        for (int o = 16; o > 0; o >>= 1) s += __shfl_xor_sync(0xffffffffu, s, o);
        float a = e / s;
        alpha_s[lane] = a;
        g_alpha[b * NSENT + lane] = a;
    }
    __syncthreads();

    // context (first half of xcat)
    for (int u = tid; u < UNITS; u += 256) {
        float c = 0.f;
#pragma unroll
        for (int s = 0; s < NSENT; s++)
            c += alpha_s[s] * encS[((size_t)(b * NSENT + s)) * UNITS + u];
        g_xcat[b * (2 * UNITS) + u] = c;
    }
}

// ---------------- word attention: per-(b,s) scores, softmax, beta ----------------
__global__ __launch_bounds__(256) void word_attn_kernel(
    const float* __restrict__ encW)    // [B, NSENT, NWORD, UNITS]
{
    __shared__ float qw_s[UNITS];
    __shared__ float sc_s[NWORD];
    __shared__ float ms_s[2];

    int bid = blockIdx.x;
    int b = bid >> 5;
    int s = bid & 31;
    int tid = threadIdx.x;
    int warp = tid >> 5, lane = tid & 31;

    for (int u = tid; u < UNITS; u += 256) qw_s[u] = g_qw[b * UNITS + u];
    __syncthreads();

    const float* base = encW + ((size_t)(b * NSENT + s)) * NWORD * UNITS;
    for (int w = warp; w < NWORD; w += 8) {
        const float4* row = (const float4*)(base + (size_t)w * UNITS);
        const float4* qv  = (const float4*)qw_s;
        float acc = 0.f;
#pragma unroll
        for (int t = 0; t < 4; t++) {
            float4 e = row[lane + t * 32];
            float4 qq = qv[lane + t * 32];
            acc += e.x * qq.x + e.y * qq.y + e.z * qq.z + e.w * qq.w;
        }
#pragma unroll
        for (int o = 16; o > 0; o >>= 1) acc += __shfl_down_sync(0xffffffffu, acc, o);
        if (lane == 0) sc_s[w] = acc;
    }
    __syncthreads();

    if (warp == 0) {
        float m = -1e30f;
        for (int i = lane; i < NWORD; i += 32) m = fmaxf(m, sc_s[i]);
#pragma unroll
        for (int o = 16; o > 0; o >>= 1) m = fmaxf(m, __shfl_xor_sync(0xffffffffu, m, o));
        float ssum = 0.f;
        for (int i = lane; i < NWORD; i += 32) ssum += expf(sc_s[i] - m);
#pragma unroll
        for (int o = 16; o > 0; o >>= 1) ssum += __shfl_xor_sync(0xffffffffu, ssum, o);
        if (lane == 0) { ms_s[0] = m; ms_s[1] = ssum; }
    }
    __syncthreads();

    if (tid < NWORD) {
        float alpha = g_alpha[b * NSENT + s];
        float v = alpha * expf(sc_s[tid] - ms_s[0]) / ms_s[1];
        g_beta[(size_t)b * (NSENT * NWORD) + s * NWORD + tid] = v;
    }
}

// ---------------- scatter copy distribution ----------------
__global__ void scatter_kernel(const int* __restrict__ numeric,
                               float* __restrict__ out)
{
    int idx = blockIdx.x * blockDim.x + threadIdx.x;  // B*1600
    if (idx >= B * NSENT * NWORD) return;
    int b = idx / (NSENT * NWORD);
    int col = numeric[idx];
    atomicAdd(&out[COPY_OFF + (size_t)b * EXT + col], g_beta[idx]);
}

// ---------------- softmax over 50000 logits ----------------
__global__ __launch_bounds__(256) void softmax_stats_kernel(const float* __restrict__ out)
{
    __shared__ float wm[8], ws[8];
    int b = blockIdx.x, tid = threadIdx.x;
    int warp = tid >> 5, lane = tid & 31;
    const float* row = out + GEN_OFF + (size_t)b * EXT;

    float m = -1e30f, s = 0.f;
    for (int v = tid; v < VOCAB; v += 256) {
        float x = row[v];
        if (x > m) { s = s * expf(m - x) + 1.f; m = x; }
        else s += expf(x - m);
    }
#pragma unroll
    for (int o = 16; o > 0; o >>= 1) {
        float m2 = __shfl_down_sync(0xffffffffu, m, o);
        float s2 = __shfl_down_sync(0xffffffffu, s, o);
        if (m2 > m) { s = s * expf(m - m2) + s2; m = m2; }
        else s += s2 * expf(m2 - m);
    }
    if (lane == 0) { wm[warp] = m; ws[warp] = s; }
    __syncthreads();
    if (tid == 0) {
        float M = wm[0], S = ws[0];
        for (int i = 1; i < 8; i++) {
            float m2 = wm[i], s2 = ws[i];
            if (m2 > M) { S = S * expf(M - m2) + s2; M = m2; }
            else S += s2 * expf(m2 - M);
        }
        g_stats[b * 2] = M;
        g_stats[b * 2 + 1] = S;
    }
}

__global__ void normalize_kernel(float* __restrict__ out)
{
    int idx = blockIdx.x * blockDim.x + threadIdx.x;   // B*EXT
    if (idx >= B * EXT) return;
    int b = idx / EXT;
    int v = idx - b * EXT;
    float* p = out + GEN_OFF + idx;
    if (v < VOCAB) {
        float m = g_stats[b * 2];
        float s = g_stats[b * 2 + 1];
        *p = expf(*p - m) / s;
    } else {
        *p = 0.f;
    }
}

// ---------------- p_gen ----------------
__global__ __launch_bounds__(128) void pgen_kernel(
    const float* __restrict__ emb,      // [B, EMB]
    const float* __restrict__ wc,       // [UNITS]
    const float* __restrict__ wh,       // [UNITS]
    const float* __restrict__ wi,       // [EMB]
    float* __restrict__ out)
{
    __shared__ float red[128];
    int b = blockIdx.x, tid = threadIdx.x;
    const float* ctx = g_xcat + b * (2 * UNITS);
    const float* dec = ctx + UNITS;
    float acc = 0.f;
    for (int k = tid; k < UNITS; k += 128) {
        acc += ctx[k] * wc[k] + dec[k] * wh[k];
        if (k < EMB) acc += emb[b * EMB + k] * wi[k];
    }
    red[tid] = acc;
    __syncthreads();
    for (int o = 64; o > 0; o >>= 1) {
        if (tid < o) red[tid] += red[tid + o];
        __syncthreads();
    }
    if (tid == 0) out[PGEN_OFF + b] = 1.f / (1.f + expf(-red[0]));
}

// ---------------- launch ----------------
extern "C" void kernel_launch(void* const* d_in, const int* in_sizes, int n_in,
                              void* d_out, int out_size)
{
    const float* emb   = (const float*)d_in[0];    // [B,1,EMB]
    const float* hid   = (const float*)d_in[1];    // [B,UNITS]
    const float* encS  = (const float*)d_in[2];    // [B,NSENT,UNITS]
    const float* encW  = (const float*)d_in[3];    // [B,NSENT,NWORD,UNITS]
    const int*   numr  = (const int*)d_in[4];      // [B, NSENT*NWORD]
    int o = (in_sizes[5] == 1) ? 6 : 5;            // skip batch_size scalar if present
    const float* gruWx = (const float*)d_in[o + 0];  // [EMB, 3U]
    const float* gruWh = (const float*)d_in[o + 1];  // [U, 3U]
    const float* grub  = (const float*)d_in[o + 2];  // [2, 3U]
    const float* WatS  = (const float*)d_in[o + 3];  // [U,U]
    const float* WatW  = (const float*)d_in[o + 4];  // [U,U]
    const float* fcW   = (const float*)d_in[o + 5];  // [U/2, VOCAB]
    const float* fcb   = (const float*)d_in[o + 6];  // [VOCAB]
    const float* wctx  = (const float*)d_in[o + 7];  // [U,1]
    const float* whid  = (const float*)d_in[o + 8];  // [U,1]
    const float* wdec  = (const float*)d_in[o + 9];  // [2U, U/2]
    const float* winp  = (const float*)d_in[o + 10]; // [U/2,1]

    float* out = (float*)d_out;

    float* xm; cudaGetSymbolAddress((void**)&xm, g_xm);
    float* hm; cudaGetSymbolAddress((void**)&hm, g_hm);
    float* q;  cudaGetSymbolAddress((void**)&q,  g_q);
    float* qw; cudaGetSymbolAddress((void**)&qw, g_qw);
    float* xcat; cudaGetSymbolAddress((void**)&xcat, g_xcat);
    float* hidden; cudaGetSymbolAddress((void**)&hidden, g_hidden);

    // 1-2. GRU pre-activations
    gemm64_kernel<<<(3 * UNITS + 127) / 128, 256>>>(emb, EMB, gruWx, 3 * UNITS, grub,
                                                    xm, 3 * UNITS, EMB, 3 * UNITS, 0);
    gemm64_kernel<<<(3 * UNITS + 127) / 128, 256>>>(hid, UNITS, gruWh, 3 * UNITS, grub + 3 * UNITS,
                                                    hm, 3 * UNITS, UNITS, 3 * UNITS, 0);
    // 3. GRU gate -> dec_output (d_out) + xcat[:,512:]
    gru_gate_kernel<<<(B * UNITS + 255) / 256, 256>>>(hid, out);
    // 4-5. attention queries
    gemm64_kernel<<<(UNITS + 127) / 128, 256>>>(out + DEC_OFF, UNITS, WatS, UNITS, nullptr,
                                                q, UNITS, UNITS, UNITS, 0);
    gemm64_kernel<<<(UNITS + 127) / 128, 256>>>(out + DEC_OFF, UNITS, WatW, UNITS, nullptr,
                                                qw, UNITS, UNITS, UNITS, 0);
    // 6. sentence attention -> alpha, context (xcat[:,:512])
    attn_sent_kernel<<<B, 256>>>(encS);
    // 7. word attention -> beta
    word_attn_kernel<<<B * NSENT, 256>>>(encW);
    // 8. copy distr: zero then scatter
    cudaMemsetAsync(out + COPY_OFF, 0, (size_t)B * EXT * sizeof(float), 0);
    scatter_kernel<<<(B * NSENT * NWORD + 255) / 256, 256>>>(numr, out);
    // 9. hidden_t = tanh(xcat @ weight_dec)
    gemm64_kernel<<<(UNITS / 2 + 127) / 128, 256>>>(xcat, 2 * UNITS, wdec, UNITS / 2, nullptr,
                                                    hidden, UNITS / 2, 2 * UNITS, UNITS / 2, 1);
    // 10. logits = hidden @ fc_W + fc_b  (into gen region, ldc=EXT)
    gemm64_kernel<<<(VOCAB + 127) / 128, 256>>>(hidden, UNITS / 2, fcW, VOCAB, fcb,
                                                out + GEN_OFF, EXT, UNITS / 2, VOCAB, 0);
    // 11-12. softmax in place + zero pad
    softmax_stats_kernel<<<B, 256>>>(out);
    normalize_kernel<<<(B * EXT + 255) / 256, 256>>>(out);
    // 13. p_gen
    pgen_kernel<<<B, 128>>>(emb, wctx, whid, winp, out);
}

// round 2
// speedup vs baseline: 1.8973x; 1.8973x over previous
#include <cuda_runtime.h>
#include <math.h>

#define B 64
#define UNITS 512
#define EMB 256
#define NSENT 32
#define NWORD 50
#define VOCAB 50000
#define OOV 100
#define EXT (VOCAB + OOV)

#define DEC_OFF   0
#define GEN_OFF   (B*UNITS)
#define COPY_OFF  (GEN_OFF + B*EXT)
#define PGEN_OFF  (COPY_OFF + B*EXT)

// ---------------- scratch ----------------
__device__ float g_xm[B * 3 * UNITS];
__device__ float g_hm[B * 3 * UNITS];
__device__ float g_q[B * UNITS];
__device__ float g_qw[B * UNITS];
__device__ float g_alpha[B * NSENT];
__device__ float g_xcat[B * 2 * UNITS];     // [context | dec]
__device__ float g_beta[B * NSENT * NWORD];
__device__ float g_hraw[B * (UNITS/2)];     // pre-tanh (zeroed, atomic split-K)
__device__ float g_hidden[B * (UNITS/2)];   // tanh applied
__device__ float g_expsum[B];               // softmax denominators (zeroed)

// ============ small GEMM, two fused jobs: C[64,N]=A[64,K]@B[K,N](+bias) ============
// tile 64x32, 256 threads, micro 4(m) x 2(n)
__global__ __launch_bounds__(256) void gemm_dual_kernel(
    const float* __restrict__ A0, int lda0, const float* __restrict__ B0, int ldb0,
    const float* __restrict__ bias0, float* __restrict__ C0, int ldc0, int K0, int nt0,
    const float* __restrict__ A1, int lda1, const float* __restrict__ B1, int ldb1,
    const float* __restrict__ bias1, float* __restrict__ C1, int ldc1, int K1)
{
    __shared__ float As[32][68];
    __shared__ float Bs[32][32];

    int bx = blockIdx.x;
    const float *A, *Bm, *bias; float* C; int lda, ldb, ldc, K, n0;
    if (bx < nt0) { A=A0; Bm=B0; bias=bias0; C=C0; lda=lda0; ldb=ldb0; ldc=ldc0; K=K0; n0=bx*32; }
    else          { A=A1; Bm=B1; bias=bias1; C=C1; lda=lda1; ldb=ldb1; ldc=ldc1; K=K1; n0=(bx-nt0)*32; }

    int tid = threadIdx.x;
    int tm = tid >> 4;          // 0..15 -> m = tm*4+jm
    int tn = tid & 15;          // 0..15 -> n = n0 + tn*2+jn

    float acc[4][2] = {};

    for (int k0 = 0; k0 < K; k0 += 32) {
#pragma unroll
        for (int i = 0; i < 8; i++) {
            int idx = i * 256 + tid;         // 2048
            int m  = idx >> 5;
            int kk = idx & 31;
            As[kk][m] = A[(size_t)m * lda + k0 + kk];
        }
        {
            int kk = tid >> 3;               // 0..31
            int c  = (tid & 7) * 4;
            *(float4*)&Bs[kk][c] = *(const float4*)(Bm + (size_t)(k0 + kk) * ldb + n0 + c);
        }
        __syncthreads();
#pragma unroll
        for (int k = 0; k < 32; k++) {
            float4 a = *(float4*)&As[k][tm * 4];
            float2 b = *(float2*)&Bs[k][tn * 2];
            acc[0][0] += a.x * b.x; acc[0][1] += a.x * b.y;
            acc[1][0] += a.y * b.x; acc[1][1] += a.y * b.y;
            acc[2][0] += a.z * b.x; acc[2][1] += a.z * b.y;
            acc[3][0] += a.w * b.x; acc[3][1] += a.w * b.y;
        }
        __syncthreads();
    }
#pragma unroll
    for (int jm = 0; jm < 4; jm++) {
        int m = tm * 4 + jm;
#pragma unroll
        for (int jn = 0; jn < 2; jn++) {
            int n = n0 + tn * 2 + jn;
            float v = acc[jm][jn];
            if (bias) v += bias[n];
            C[(size_t)m * ldc + n] = v;
        }
    }
}

// ============ split-K GEMM for weight_dec: atomicAdd into zeroed g_hraw ============
__global__ __launch_bounds__(256) void gemm_splitk_kernel(
    const float* __restrict__ A, int lda, const float* __restrict__ Bm, int ldb,
    float* __restrict__ C, int ldc, int Ktot, int ksplit)
{
    __shared__ float As[32][68];
    __shared__ float Bs[32][32];
    int tid = threadIdx.x;
    int tm = tid >> 4, tn = tid & 15;
    int n0 = blockIdx.x * 32;
    int kbase = blockIdx.y * ksplit;

    float acc[4][2] = {};
    for (int kc = 0; kc < ksplit; kc += 32) {
        int k0 = kbase + kc;
#pragma unroll
        for (int i = 0; i < 8; i++) {
            int idx = i * 256 + tid;
            int m  = idx >> 5;
            int kk = idx & 31;
            As[kk][m] = A[(size_t)m * lda + k0 + kk];
        }
        {
            int kk = tid >> 3;
            int c  = (tid & 7) * 4;
            *(float4*)&Bs[kk][c] = *(const float4*)(Bm + (size_t)(k0 + kk) * ldb + n0 + c);
        }
        __syncthreads();
#pragma unroll
        for (int k = 0; k < 32; k++) {
            float4 a = *(float4*)&As[k][tm * 4];
            float2 b = *(float2*)&Bs[k][tn * 2];
            acc[0][0] += a.x * b.x; acc[0][1] += a.x * b.y;
            acc[1][0] += a.y * b.x; acc[1][1] += a.y * b.y;
            acc[2][0] += a.z * b.x; acc[2][1] += a.z * b.y;
            acc[3][0] += a.w * b.x; acc[3][1] += a.w * b.y;
        }
        __syncthreads();
    }
#pragma unroll
    for (int jm = 0; jm < 4; jm++) {
        int m = tm * 4 + jm;
#pragma unroll
        for (int jn = 0; jn < 2; jn++)
            atomicAdd(&C[(size_t)m * ldc + n0 + tn * 2 + jn], acc[jm][jn]);
    }
}

__global__ void tanh_kernel() {
    int i = blockIdx.x * blockDim.x + threadIdx.x;
    if (i < B * (UNITS/2)) g_hidden[i] = tanhf(g_hraw[i]);
}

// ============ fc GEMM: out = exp(hidden@fcW + fcb), per-row exp-sum atomics ============
// tile 64x128, 256 threads, micro 4x8, K=256
__global__ __launch_bounds__(256) void fc_gemm_kernel(
    const float* __restrict__ Bm,      // fcW [256, 50000]
    const float* __restrict__ bias,    // fcb
    float* __restrict__ out)
{
    __shared__ float As[32][68];
    __shared__ float Bs[32][128];
    __shared__ float red[64][17];

    int tid = threadIdx.x;
    int tm = tid >> 4;      // 0..15
    int tc = tid & 15;      // 0..15
    int n0 = blockIdx.x * 128;

    float acc[4][8] = {};

#pragma unroll
    for (int c0 = 0; c0 < 256; c0 += 32) {
#pragma unroll
        for (int i = 0; i < 8; i++) {
            int idx = i * 256 + tid;
            int m  = idx >> 5;
            int kk = idx & 31;
            As[kk][m] = g_hidden[m * 256 + c0 + kk];
        }
#pragma unroll
        for (int i = 0; i < 4; i++) {
            int v  = i * 256 + tid;
            int kk = v >> 5;
            int c  = (v & 31) * 4;
            int n  = n0 + c;
            float4 val = (n < VOCAB) ? *(const float4*)(Bm + (size_t)(c0 + kk) * VOCAB + n)
                                     : make_float4(0.f, 0.f, 0.f, 0.f);
            *(float4*)&Bs[kk][c] = val;
        }
        __syncthreads();
#pragma unroll
        for (int k = 0; k < 32; k++) {
            float4 a  = *(float4*)&As[k][tm * 4];
            float4 b0 = *(float4*)&Bs[k][tc * 8];
            float4 b1 = *(float4*)&Bs[k][tc * 8 + 4];
            float av[4] = {a.x, a.y, a.z, a.w};
            float bv[8] = {b0.x, b0.y, b0.z, b0.w, b1.x, b1.y, b1.z, b1.w};
#pragma unroll
            for (int jm = 0; jm < 4; jm++)
#pragma unroll
                for (int jn = 0; jn < 8; jn++)
                    acc[jm][jn] += av[jm] * bv[jn];
        }
        __syncthreads();
    }

    float rowsum[4] = {};
#pragma unroll
    for (int jm = 0; jm < 4; jm++) {
        int m = tm * 4 + jm;
#pragma unroll
        for (int jn = 0; jn < 8; jn++) {
            int n = n0 + tc * 8 + jn;
            if (n < VOCAB) {
                float e = __expf(acc[jm][jn] + bias[n]);
                out[GEN_OFF + (size_t)m * EXT + n] = e;
                rowsum[jm] += e;
            }
        }
    }
#pragma unroll
    for (int jm = 0; jm < 4; jm++) red[tm * 4 + jm][tc] = rowsum[jm];
    __syncthreads();
    if (tid < 64) {
        float s = 0.f;
#pragma unroll
        for (int i = 0; i < 16; i++) s += red[tid][i];
        atomicAdd(&g_expsum[tid], s);
    }
}

__global__ void normalize_kernel(float* __restrict__ out) {
    int idx = blockIdx.x * blockDim.x + threadIdx.x;
    if (idx >= B * EXT) return;
    int b = idx / EXT;
    int v = idx - b * EXT;
    float* p = out + GEN_OFF + idx;
    *p = (v < VOCAB) ? (*p) * (1.f / g_expsum[b]) : 0.f;
}

// ---------------- GRU gate ----------------
__global__ void gru_gate_kernel(const float* __restrict__ hprev, float* __restrict__ out) {
    int idx = blockIdx.x * blockDim.x + threadIdx.x;
    if (idx >= B * UNITS) return;
    int b = idx >> 9, u = idx & 511;
    const float* xm = g_xm + b * (3 * UNITS);
    const float* hm = g_hm + b * (3 * UNITS);
    float z  = 1.f / (1.f + __expf(-(xm[u] + hm[u])));
    float r  = 1.f / (1.f + __expf(-(xm[UNITS + u] + hm[UNITS + u])));
    float hc = tanhf(xm[2 * UNITS + u] + r * hm[2 * UNITS + u]);
    float h  = hprev[idx];
    float hn = z * h + (1.f - z) * hc;
    out[DEC_OFF + idx] = hn;
    g_xcat[b * (2 * UNITS) + UNITS + u] = hn;
}

// ---------------- sentence attention ----------------
__global__ __launch_bounds__(256) void attn_sent_kernel(const float* __restrict__ encS) {
    __shared__ float q_s[UNITS];
    __shared__ float sc_s[NSENT];
    __shared__ float alpha_s[NSENT];
    int b = blockIdx.x, tid = threadIdx.x;
    int warp = tid >> 5, lane = tid & 31;

    for (int u = tid; u < UNITS; u += 256) q_s[u] = g_q[b * UNITS + u];
    __syncthreads();
#pragma unroll
    for (int i = 0; i < 4; i++) {
        int s = warp * 4 + i;
        const float4* row = (const float4*)(encS + ((size_t)(b * NSENT + s)) * UNITS);
        const float4* qv  = (const float4*)q_s;
        float acc = 0.f;
#pragma unroll
        for (int t = 0; t < 4; t++) {
            float4 e = row[lane + t * 32], qq = qv[lane + t * 32];
            acc += e.x*qq.x + e.y*qq.y + e.z*qq.z + e.w*qq.w;
        }
#pragma unroll
        for (int o = 16; o > 0; o >>= 1) acc += __shfl_down_sync(0xffffffffu, acc, o);
        if (lane == 0) sc_s[s] = acc;
    }
    __syncthreads();
    if (warp == 0) {
        float x = sc_s[lane], m = x;
#pragma unroll
        for (int o = 16; o > 0; o >>= 1) m = fmaxf(m, __shfl_xor_sync(0xffffffffu, m, o));
        float e = __expf(x - m), s = e;
#pragma unroll
        for (int o = 16; o > 0; o >>= 1) s += __shfl_xor_sync(0xffffffffu, s, o);
        float a = e / s;
        alpha_s[lane] = a;
        g_alpha[b * NSENT + lane] = a;
    }
    __syncthreads();
    for (int u = tid; u < UNITS; u += 256) {
        float c = 0.f;
#pragma unroll
        for (int s = 0; s < NSENT; s++)
            c += alpha_s[s] * encS[((size_t)(b * NSENT + s)) * UNITS + u];
        g_xcat[b * (2 * UNITS) + u] = c;
    }
}

// ---------------- word attention ----------------
__global__ __launch_bounds__(256) void word_attn_kernel(const float* __restrict__ encW) {
    __shared__ float qw_s[UNITS];
    __shared__ float sc_s[NWORD];
    __shared__ float ms_s[2];
    int bid = blockIdx.x;
    int b = bid >> 5, s = bid & 31;
    int tid = threadIdx.x, warp = tid >> 5, lane = tid & 31;

    for (int u = tid; u < UNITS; u += 256) qw_s[u] = g_qw[b * UNITS + u];
    __syncthreads();
    const float* base = encW + ((size_t)(b * NSENT + s)) * NWORD * UNITS;
    for (int w = warp; w < NWORD; w += 8) {
        const float4* row = (const float4*)(base + (size_t)w * UNITS);
        const float4* qv  = (const float4*)qw_s;
        float acc = 0.f;
#pragma unroll
        for (int t = 0; t < 4; t++) {
            float4 e = row[lane + t * 32], qq = qv[lane + t * 32];
            acc += e.x*qq.x + e.y*qq.y + e.z*qq.z + e.w*qq.w;
        }
#pragma unroll
        for (int o = 16; o > 0; o >>= 1) acc += __shfl_down_sync(0xffffffffu, acc, o);
        if (lane == 0) sc_s[w] = acc;
    }
    __syncthreads();
    if (warp == 0) {
        float m = -1e30f;
        for (int i = lane; i < NWORD; i += 32) m = fmaxf(m, sc_s[i]);
#pragma unroll
        for (int o = 16; o > 0; o >>= 1) m = fmaxf(m, __shfl_xor_sync(0xffffffffu, m, o));
        float ssum = 0.f;
        for (int i = lane; i < NWORD; i += 32) ssum += __expf(sc_s[i] - m);
#pragma unroll
        for (int o = 16; o > 0; o >>= 1) ssum += __shfl_xor_sync(0xffffffffu, ssum, o);
        if (lane == 0) { ms_s[0] = m; ms_s[1] = ssum; }
    }
    __syncthreads();
    if (tid < NWORD) {
        float alpha = g_alpha[b * NSENT + s];
        g_beta[(size_t)b * (NSENT * NWORD) + s * NWORD + tid] =
            alpha * __expf(sc_s[tid] - ms_s[0]) / ms_s[1];
    }
}

__global__ void scatter_kernel(const int* __restrict__ numeric, float* __restrict__ out) {
    int idx = blockIdx.x * blockDim.x + threadIdx.x;
    if (idx >= B * NSENT * NWORD) return;
    int b = idx / (NSENT * NWORD);
    atomicAdd(&out[COPY_OFF + (size_t)b * EXT + numeric[idx]], g_beta[idx]);
}

__global__ __launch_bounds__(128) void pgen_kernel(
    const float* __restrict__ emb, const float* __restrict__ wc,
    const float* __restrict__ wh, const float* __restrict__ wi,
    float* __restrict__ out)
{
    __shared__ float red[128];
    int b = blockIdx.x, tid = threadIdx.x;
    const float* ctx = g_xcat + b * (2 * UNITS);
    const float* dec = ctx + UNITS;
    float acc = 0.f;
    for (int k = tid; k < UNITS; k += 128) {
        acc += ctx[k] * wc[k] + dec[k] * wh[k];
        if (k < EMB) acc += emb[b * EMB + k] * wi[k];
    }
    red[tid] = acc;
    __syncthreads();
    for (int o = 64; o > 0; o >>= 1) {
        if (tid < o) red[tid] += red[tid + o];
        __syncthreads();
    }
    if (tid == 0) out[PGEN_OFF + b] = 1.f / (1.f + __expf(-red[0]));
}

// ---------------- launch ----------------
extern "C" void kernel_launch(void* const* d_in, const int* in_sizes, int n_in,
                              void* d_out, int out_size)
{
    const float* emb   = (const float*)d_in[0];
    const float* hid   = (const float*)d_in[1];
    const float* encS  = (const float*)d_in[2];
    const float* encW  = (const float*)d_in[3];
    const int*   numr  = (const int*)d_in[4];
    int o = (in_sizes[5] == 1) ? 6 : 5;
    const float* gruWx = (const float*)d_in[o + 0];
    const float* gruWh = (const float*)d_in[o + 1];
    const float* grub  = (const float*)d_in[o + 2];
    const float* WatS  = (const float*)d_in[o + 3];
    const float* WatW  = (const float*)d_in[o + 4];
    const float* fcW   = (const float*)d_in[o + 5];
    const float* fcb   = (const float*)d_in[o + 6];
    const float* wctx  = (const float*)d_in[o + 7];
    const float* whid  = (const float*)d_in[o + 8];
    const float* wdec  = (const float*)d_in[o + 9];
    const float* winp  = (const float*)d_in[o + 10];

    float* out = (float*)d_out;

    float *xm, *hm, *q, *qw, *xcat, *hraw, *expsum;
    cudaGetSymbolAddress((void**)&xm, g_xm);
    cudaGetSymbolAddress((void**)&hm, g_hm);
    cudaGetSymbolAddress((void**)&q,  g_q);
    cudaGetSymbolAddress((void**)&qw, g_qw);
    cudaGetSymbolAddress((void**)&xcat, g_xcat);
    cudaGetSymbolAddress((void**)&hraw, g_hraw);
    cudaGetSymbolAddress((void**)&expsum, g_expsum);

    // independent zeroing first
    cudaMemsetAsync(out + COPY_OFF, 0, (size_t)B * EXT * sizeof(float), 0);
    cudaMemsetAsync(hraw, 0, B * (UNITS/2) * sizeof(float), 0);
    cudaMemsetAsync(expsum, 0, B * sizeof(float), 0);

    // GRU pre-activations: xm (K=256) + hm (K=512), fused
    gemm_dual_kernel<<<96, 256>>>(
        emb, EMB, gruWx, 3*UNITS, grub,           xm, 3*UNITS, EMB, 48,
        hid, UNITS, gruWh, 3*UNITS, grub+3*UNITS, hm, 3*UNITS, UNITS);
    gru_gate_kernel<<<(B*UNITS + 255)/256, 256>>>(hid, out);
    // attention queries q + qw, fused
    gemm_dual_kernel<<<32, 256>>>(
        out + DEC_OFF, UNITS, WatS, UNITS, nullptr, q,  UNITS, UNITS, 16,
        out + DEC_OFF, UNITS, WatW, UNITS, nullptr, qw, UNITS, UNITS);
    attn_sent_kernel<<<B, 256>>>(encS);
    word_attn_kernel<<<B * NSENT, 256>>>(encW);
    scatter_kernel<<<(B*NSENT*NWORD + 255)/256, 256>>>(numr, out);
    // hidden = tanh(xcat @ wdec): split-K=4
    gemm_splitk_kernel<<<dim3(8, 4), 256>>>(xcat, 2*UNITS, wdec, UNITS/2, hraw, UNITS/2, 2*UNITS, 256);
    tanh_kernel<<<(B*(UNITS/2) + 255)/256, 256>>>();
    // logits -> exp + per-row sums
    fc_gemm_kernel<<<(VOCAB + 127)/128, 256>>>(fcW, fcb, out);
    normalize_kernel<<<(B*EXT + 255)/256, 256>>>(out);
    pgen_kernel<<<B, 128>>>(emb, wctx, whid, winp, out);
}

// round 3
// speedup vs baseline: 2.3064x; 1.2156x over previous
#include <cuda_runtime.h>
#include <math.h>

#define B 64
#define UNITS 512
#define EMB 256
#define NSENT 32
#define NWORD 50
#define VOCAB 50000
#define OOV 100
#define EXT (VOCAB + OOV)

#define DEC_OFF   0
#define GEN_OFF   (B*UNITS)
#define COPY_OFF  (GEN_OFF + B*EXT)
#define PGEN_OFF  (COPY_OFF + B*EXT)

// ---------------- scratch ----------------
__device__ float g_xm[B * 3 * UNITS];
__device__ float g_hm[B * 3 * UNITS];
__device__ float g_q[B * UNITS];
__device__ float g_qw[B * UNITS];
__device__ float g_alpha[B * NSENT];
__device__ float g_xcat[B * 2 * UNITS];     // [context | dec]
__device__ float g_hraw[B * (UNITS/2)];     // pre-tanh (zeroed, atomic split-K)
__device__ float g_hidden[B * (UNITS/2)];
__device__ float g_expsum[B];

// ============ small GEMM, two fused jobs: C[64,N]=A[64,K]@B[K,N](+bias) ============
__global__ __launch_bounds__(256) void gemm_dual_kernel(
    const float* __restrict__ A0, int lda0, const float* __restrict__ B0, int ldb0,
    const float* __restrict__ bias0, float* __restrict__ C0, int ldc0, int K0, int nt0,
    const float* __restrict__ A1, int lda1, const float* __restrict__ B1, int ldb1,
    const float* __restrict__ bias1, float* __restrict__ C1, int ldc1, int K1)
{
    __shared__ float As[32][68];
    __shared__ float Bs[32][32];

    int bx = blockIdx.x;
    const float *A, *Bm, *bias; float* C; int lda, ldb, ldc, K, n0;
    if (bx < nt0) { A=A0; Bm=B0; bias=bias0; C=C0; lda=lda0; ldb=ldb0; ldc=ldc0; K=K0; n0=bx*32; }
    else          { A=A1; Bm=B1; bias=bias1; C=C1; lda=lda1; ldb=ldb1; ldc=ldc1; K=K1; n0=(bx-nt0)*32; }

    int tid = threadIdx.x;
    int tm = tid >> 4, tn = tid & 15;
    float acc[4][2] = {};

    for (int k0 = 0; k0 < K; k0 += 32) {
#pragma unroll
        for (int i = 0; i < 8; i++) {
            int idx = i * 256 + tid;
            int m  = idx >> 5;
            int kk = idx & 31;
            As[kk][m] = A[(size_t)m * lda + k0 + kk];
        }
        {
            int kk = tid >> 3;
            int c  = (tid & 7) * 4;
            *(float4*)&Bs[kk][c] = *(const float4*)(Bm + (size_t)(k0 + kk) * ldb + n0 + c);
        }
        __syncthreads();
#pragma unroll
        for (int k = 0; k < 32; k++) {
            float4 a = *(float4*)&As[k][tm * 4];
            float2 b = *(float2*)&Bs[k][tn * 2];
            acc[0][0] += a.x * b.x; acc[0][1] += a.x * b.y;
            acc[1][0] += a.y * b.x; acc[1][1] += a.y * b.y;
            acc[2][0] += a.z * b.x; acc[2][1] += a.z * b.y;
            acc[3][0] += a.w * b.x; acc[3][1] += a.w * b.y;
        }
        __syncthreads();
    }
#pragma unroll
    for (int jm = 0; jm < 4; jm++) {
        int m = tm * 4 + jm;
#pragma unroll
        for (int jn = 0; jn < 2; jn++) {
            int n = n0 + tn * 2 + jn;
            float v = acc[jm][jn];
            if (bias) v += bias[n];
            C[(size_t)m * ldc + n] = v;
        }
    }
}

// ============ split-K GEMM for weight_dec ============
__global__ __launch_bounds__(256) void gemm_splitk_kernel(
    const float* __restrict__ A, int lda, const float* __restrict__ Bm, int ldb,
    float* __restrict__ C, int ldc, int ksplit)
{
    __shared__ float As[32][68];
    __shared__ float Bs[32][32];
    int tid = threadIdx.x;
    int tm = tid >> 4, tn = tid & 15;
    int n0 = blockIdx.x * 32;
    int kbase = blockIdx.y * ksplit;

    float acc[4][2] = {};
    for (int kc = 0; kc < ksplit; kc += 32) {
        int k0 = kbase + kc;
#pragma unroll
        for (int i = 0; i < 8; i++) {
            int idx = i * 256 + tid;
            int m  = idx >> 5;
            int kk = idx & 31;
            As[kk][m] = A[(size_t)m * lda + k0 + kk];
        }
        {
            int kk = tid >> 3;
            int c  = (tid & 7) * 4;
            *(float4*)&Bs[kk][c] = *(const float4*)(Bm + (size_t)(k0 + kk) * ldb + n0 + c);
        }
        __syncthreads();
#pragma unroll
        for (int k = 0; k < 32; k++) {
            float4 a = *(float4*)&As[k][tm * 4];
            float2 b = *(float2*)&Bs[k][tn * 2];
            acc[0][0] += a.x * b.x; acc[0][1] += a.x * b.y;
            acc[1][0] += a.y * b.x; acc[1][1] += a.y * b.y;
            acc[2][0] += a.z * b.x; acc[2][1] += a.z * b.y;
            acc[3][0] += a.w * b.x; acc[3][1] += a.w * b.y;
        }
        __syncthreads();
    }
#pragma unroll
    for (int jm = 0; jm < 4; jm++) {
        int m = tm * 4 + jm;
#pragma unroll
        for (int jn = 0; jn < 2; jn++)
            atomicAdd(&C[(size_t)m * ldc + n0 + tn * 2 + jn], acc[jm][jn]);
    }
}

__global__ void tanh_kernel() {
    int i = blockIdx.x * blockDim.x + threadIdx.x;
    if (i < B * (UNITS/2)) g_hidden[i] = tanhf(g_hraw[i]);
}

// ============ fc GEMM: packed f32x2 FFMA, exp epilogue + per-row exp sums ============
__global__ __launch_bounds__(256) void fc_gemm_kernel(
    const float* __restrict__ Bm,      // fcW [256, 50000]
    const float* __restrict__ bias,
    float* __restrict__ out)
{
    __shared__ float As2[32][132];     // duplicated pairs: [k][2m]=[k][2m+1]=A[m][k]
    __shared__ float Bs[32][128];
    __shared__ float red[64][17];

    int tid = threadIdx.x;
    int tm = tid >> 4;      // 0..15
    int tc = tid & 15;      // 0..15
    int n0 = blockIdx.x * 128;

    unsigned long long acc[4][4];
#pragma unroll
    for (int i = 0; i < 4; i++)
#pragma unroll
        for (int j = 0; j < 4; j++) acc[i][j] = 0ULL;

#pragma unroll
    for (int c0 = 0; c0 < 256; c0 += 32) {
#pragma unroll
        for (int i = 0; i < 8; i++) {
            int idx = i * 256 + tid;
            int m  = idx >> 5;
            int kk = idx & 31;
            float v = g_hidden[m * 256 + c0 + kk];
            *(float2*)&As2[kk][2 * m] = make_float2(v, v);
        }
#pragma unroll
        for (int i = 0; i < 4; i++) {
            int v  = i * 256 + tid;
            int kk = v >> 5;
            int c  = (v & 31) * 4;
            int n  = n0 + c;
            float4 val = (n < VOCAB) ? *(const float4*)(Bm + (size_t)(c0 + kk) * VOCAB + n)
                                     : make_float4(0.f, 0.f, 0.f, 0.f);
            *(float4*)&Bs[kk][c] = val;
        }
        __syncthreads();
#pragma unroll
        for (int k = 0; k < 32; k++) {
            ulonglong2 aA = *(const ulonglong2*)&As2[k][tm * 8];
            ulonglong2 aB = *(const ulonglong2*)&As2[k][tm * 8 + 4];
            ulonglong2 b01 = *(const ulonglong2*)&Bs[k][tc * 8];
            ulonglong2 b23 = *(const ulonglong2*)&Bs[k][tc * 8 + 4];
            unsigned long long ap0 = aA.x, ap1 = aA.y, ap2 = aB.x, ap3 = aB.y;
            unsigned long long bp0 = b01.x, bp1 = b01.y, bp2 = b23.x, bp3 = b23.y;
#define FMA2(d, a, b) asm volatile("fma.rn.f32x2 %0, %1, %2, %0;" : "+l"(d) : "l"(a), "l"(b))
            FMA2(acc[0][0], ap0, bp0); FMA2(acc[0][1], ap0, bp1);
            FMA2(acc[0][2], ap0, bp2); FMA2(acc[0][3], ap0, bp3);
            FMA2(acc[1][0], ap1, bp0); FMA2(acc[1][1], ap1, bp1);
            FMA2(acc[1][2], ap1, bp2); FMA2(acc[1][3], ap1, bp3);
            FMA2(acc[2][0], ap2, bp0); FMA2(acc[2][1], ap2, bp1);
            FMA2(acc[2][2], ap2, bp2); FMA2(acc[2][3], ap2, bp3);
            FMA2(acc[3][0], ap3, bp0); FMA2(acc[3][1], ap3, bp1);
            FMA2(acc[3][2], ap3, bp2); FMA2(acc[3][3], ap3, bp3);
#undef FMA2
        }
        __syncthreads();
    }

    float rowsum[4] = {};
#pragma unroll
    for (int jm = 0; jm < 4; jm++) {
        int m = tm * 4 + jm;
#pragma unroll
        for (int jp = 0; jp < 4; jp++) {
            int n = n0 + tc * 8 + jp * 2;
            unsigned long long v = acc[jm][jp];
            if (n < VOCAB) {
                float e = __expf(__uint_as_float((unsigned)v) + bias[n]);
                out[GEN_OFF + (size_t)m * EXT + n] = e;
                rowsum[jm] += e;
            }
            if (n + 1 < VOCAB) {
                float e = __expf(__uint_as_float((unsigned)(v >> 32)) + bias[n + 1]);
                out[GEN_OFF + (size_t)m * EXT + n + 1] = e;
                rowsum[jm] += e;
            }
        }
    }
#pragma unroll
    for (int jm = 0; jm < 4; jm++) red[tm * 4 + jm][tc] = rowsum[jm];
    __syncthreads();
    if (tid < 64) {
        float s = 0.f;
#pragma unroll
        for (int i = 0; i < 16; i++) s += red[tid][i];
        atomicAdd(&g_expsum[tid], s);
    }
}

__global__ void normalize_kernel(float* __restrict__ out) {
    int idx = blockIdx.x * blockDim.x + threadIdx.x;
    if (idx >= B * EXT) return;
    int b = idx / EXT;
    int v = idx - b * EXT;
    float* p = out + GEN_OFF + idx;
    *p = (v < VOCAB) ? (*p) * (1.f / g_expsum[b]) : 0.f;
}

// ---------------- GRU gate ----------------
__global__ void gru_gate_kernel(const float* __restrict__ hprev, float* __restrict__ out) {
    int idx = blockIdx.x * blockDim.x + threadIdx.x;
    if (idx >= B * UNITS) return;
    int b = idx >> 9, u = idx & 511;
    const float* xm = g_xm + b * (3 * UNITS);
    const float* hm = g_hm + b * (3 * UNITS);
    float z  = 1.f / (1.f + __expf(-(xm[u] + hm[u])));
    float r  = 1.f / (1.f + __expf(-(xm[UNITS + u] + hm[UNITS + u])));
    float hc = tanhf(xm[2 * UNITS + u] + r * hm[2 * UNITS + u]);
    float h  = hprev[idx];
    float hn = z * h + (1.f - z) * hc;
    out[DEC_OFF + idx] = hn;
    g_xcat[b * (2 * UNITS) + UNITS + u] = hn;
}

// ---------------- sentence attention (512 threads) ----------------
__global__ __launch_bounds__(512) void attn_sent_kernel(const float* __restrict__ encS) {
    __shared__ float q_s[UNITS];
    __shared__ float sc_s[NSENT];
    __shared__ float alpha_s[NSENT];
    int b = blockIdx.x, tid = threadIdx.x;
    int warp = tid >> 5, lane = tid & 31;

    q_s[tid] = g_q[b * UNITS + tid];
    __syncthreads();
#pragma unroll
    for (int i = 0; i < 2; i++) {
        int s = warp * 2 + i;
        const float4* row = (const float4*)(encS + ((size_t)(b * NSENT + s)) * UNITS);
        const float4* qv  = (const float4*)q_s;
        float acc = 0.f;
#pragma unroll
        for (int t = 0; t < 4; t++) {
            float4 e = row[lane + t * 32], qq = qv[lane + t * 32];
            acc += e.x*qq.x + e.y*qq.y + e.z*qq.z + e.w*qq.w;
        }
#pragma unroll
        for (int o = 16; o > 0; o >>= 1) acc += __shfl_down_sync(0xffffffffu, acc, o);
        if (lane == 0) sc_s[s] = acc;
    }
    __syncthreads();
    if (warp == 0) {
        float x = sc_s[lane], m = x;
#pragma unroll
        for (int o = 16; o > 0; o >>= 1) m = fmaxf(m, __shfl_xor_sync(0xffffffffu, m, o));
        float e = __expf(x - m), s = e;
#pragma unroll
        for (int o = 16; o > 0; o >>= 1) s += __shfl_xor_sync(0xffffffffu, s, o);
        float a = e / s;
        alpha_s[lane] = a;
        g_alpha[b * NSENT + lane] = a;
    }
    __syncthreads();
    {
        float c = 0.f;
#pragma unroll
        for (int s = 0; s < NSENT; s++)
            c += alpha_s[s] * encS[((size_t)(b * NSENT + s)) * UNITS + tid];
        g_xcat[b * (2 * UNITS) + tid] = c;
    }
}

// ---------------- word attention + fused scatter ----------------
__global__ __launch_bounds__(256) void word_attn_scatter_kernel(
    const float* __restrict__ encW, const int* __restrict__ numeric,
    float* __restrict__ out)
{
    __shared__ float qw_s[UNITS];
    __shared__ float sc_s[NWORD];
    __shared__ float ms_s[2];
    int bid = blockIdx.x;
    int b = bid >> 5, s = bid & 31;
    int tid = threadIdx.x, warp = tid >> 5, lane = tid & 31;

    for (int u = tid; u < UNITS; u += 256) qw_s[u] = g_qw[b * UNITS + u];
    __syncthreads();
    const float* base = encW + ((size_t)(b * NSENT + s)) * NWORD * UNITS;
    for (int w = warp; w < NWORD; w += 8) {
        const float4* row = (const float4*)(base + (size_t)w * UNITS);
        const float4* qv  = (const float4*)qw_s;
        float acc = 0.f;
#pragma unroll
        for (int t = 0; t < 4; t++) {
            float4 e = row[lane + t * 32], qq = qv[lane + t * 32];
            acc += e.x*qq.x + e.y*qq.y + e.z*qq.z + e.w*qq.w;
        }
#pragma unroll
        for (int o = 16; o > 0; o >>= 1) acc += __shfl_down_sync(0xffffffffu, acc, o);
        if (lane == 0) sc_s[w] = acc;
    }
    __syncthreads();
    if (warp == 0) {
        float m = -1e30f;
        for (int i = lane; i < NWORD; i += 32) m = fmaxf(m, sc_s[i]);
#pragma unroll
        for (int o = 16; o > 0; o >>= 1) m = fmaxf(m, __shfl_xor_sync(0xffffffffu, m, o));
        float ssum = 0.f;
        for (int i = lane; i < NWORD; i += 32) ssum += __expf(sc_s[i] - m);
#pragma unroll
        for (int o = 16; o > 0; o >>= 1) ssum += __shfl_xor_sync(0xffffffffu, ssum, o);
        if (lane == 0) { ms_s[0] = m; ms_s[1] = ssum; }
    }
    __syncthreads();
    if (tid < NWORD) {
        float alpha = g_alpha[b * NSENT + s];
        float v = alpha * __expf(sc_s[tid] - ms_s[0]) / ms_s[1];
        int col = numeric[b * (NSENT * NWORD) + s * NWORD + tid];
        atomicAdd(&out[COPY_OFF + (size_t)b * EXT + col], v);
    }
}

__global__ __launch_bounds__(128) void pgen_kernel(
    const float* __restrict__ emb, const float* __restrict__ wc,
    const float* __restrict__ wh, const float* __restrict__ wi,
    float* __restrict__ out)
{
    __shared__ float red[128];
    int b = blockIdx.x, tid = threadIdx.x;
    const float* ctx = g_xcat + b * (2 * UNITS);
    const float* dec = ctx + UNITS;
    float acc = 0.f;
    for (int k = tid; k < UNITS; k += 128) {
        acc += ctx[k] * wc[k] + dec[k] * wh[k];
        if (k < EMB) acc += emb[b * EMB + k] * wi[k];
    }
    red[tid] = acc;
    __syncthreads();
    for (int o = 64; o > 0; o >>= 1) {
        if (tid < o) red[tid] += red[tid + o];
        __syncthreads();
    }
    if (tid == 0) out[PGEN_OFF + b] = 1.f / (1.f + __expf(-red[0]));
}

// ---------------- launch ----------------
extern "C" void kernel_launch(void* const* d_in, const int* in_sizes, int n_in,
                              void* d_out, int out_size)
{
    const float* emb   = (const float*)d_in[0];
    const float* hid   = (const float*)d_in[1];
    const float* encS  = (const float*)d_in[2];
    const float* encW  = (const float*)d_in[3];
    const int*   numr  = (const int*)d_in[4];
    int o = (in_sizes[5] == 1) ? 6 : 5;
    const float* gruWx = (const float*)d_in[o + 0];
    const float* gruWh = (const float*)d_in[o + 1];
    const float* grub  = (const float*)d_in[o + 2];
    const float* WatS  = (const float*)d_in[o + 3];
    const float* WatW  = (const float*)d_in[o + 4];
    const float* fcW   = (const float*)d_in[o + 5];
    const float* fcb   = (const float*)d_in[o + 6];
    const float* wctx  = (const float*)d_in[o + 7];
    const float* whid  = (const float*)d_in[o + 8];
    const float* wdec  = (const float*)d_in[o + 9];
    const float* winp  = (const float*)d_in[o + 10];

    float* out = (float*)d_out;

    float *xm, *hm, *q, *qw, *xcat, *hraw, *expsum;
    cudaGetSymbolAddress((void**)&xm, g_xm);
    cudaGetSymbolAddress((void**)&hm, g_hm);
    cudaGetSymbolAddress((void**)&q,  g_q);
    cudaGetSymbolAddress((void**)&qw, g_qw);
    cudaGetSymbolAddress((void**)&xcat, g_xcat);
    cudaGetSymbolAddress((void**)&hraw, g_hraw);
    cudaGetSymbolAddress((void**)&expsum, g_expsum);

    static cudaStream_t s1 = nullptr;
    static cudaEvent_t ev_fork = nullptr, ev_alpha = nullptr, ev_join = nullptr;
    if (!s1) {
        cudaStreamCreateWithFlags(&s1, cudaStreamNonBlocking);
        cudaEventCreateWithFlags(&ev_fork,  cudaEventDisableTiming);
        cudaEventCreateWithFlags(&ev_alpha, cudaEventDisableTiming);
        cudaEventCreateWithFlags(&ev_join,  cudaEventDisableTiming);
    }

    // fork: side stream zeroes copy region while main chain starts
    cudaEventRecord(ev_fork, 0);
    cudaStreamWaitEvent(s1, ev_fork, 0);
    cudaMemsetAsync(out + COPY_OFF, 0, (size_t)B * EXT * sizeof(float), s1);

    cudaMemsetAsync(hraw, 0, B * (UNITS/2) * sizeof(float), 0);
    cudaMemsetAsync(expsum, 0, B * sizeof(float), 0);

    // GRU pre-activations (fused)
    gemm_dual_kernel<<<96, 256>>>(
        emb, EMB, gruWx, 3*UNITS, grub,           xm, 3*UNITS, EMB, 48,
        hid, UNITS, gruWh, 3*UNITS, grub+3*UNITS, hm, 3*UNITS, UNITS);
    gru_gate_kernel<<<(B*UNITS + 255)/256, 256>>>(hid, out);
    // attention queries (fused)
    gemm_dual_kernel<<<32, 256>>>(
        out + DEC_OFF, UNITS, WatS, UNITS, nullptr, q,  UNITS, UNITS, 16,
        out + DEC_OFF, UNITS, WatW, UNITS, nullptr, qw, UNITS, UNITS);
    attn_sent_kernel<<<B, 512>>>(encS);
    cudaEventRecord(ev_alpha, 0);

    // side stream: word attention + scatter + p_gen (independent of fc chain)
    cudaStreamWaitEvent(s1, ev_alpha, 0);
    word_attn_scatter_kernel<<<B * NSENT, 256, 0, s1>>>(encW, numr, out);
    pgen_kernel<<<B, 128, 0, s1>>>(emb, wctx, whid, winp, out);
    cudaEventRecord(ev_join, s1);

    // main chain: hidden -> fc -> normalize
    gemm_splitk_kernel<<<dim3(8, 8), 256>>>(xcat, 2*UNITS, wdec, UNITS/2, hraw, UNITS/2, 128);
    tanh_kernel<<<(B*(UNITS/2) + 255)/256, 256>>>();
    fc_gemm_kernel<<<(VOCAB + 127)/128, 256>>>(fcW, fcb, out);
    normalize_kernel<<<(B*EXT + 255)/256, 256>>>(out);

    cudaStreamWaitEvent(0, ev_join, 0);
}

// round 6
// speedup vs baseline: 2.3150x; 1.0037x over previous
#include <cuda_runtime.h>
#include <math.h>
#include <stdint.h>

#define B 64
#define UNITS 512
#define EMB 256
#define NSENT 32
#define NWORD 50
#define VOCAB 50000
#define OOV 100
#define EXT (VOCAB + OOV)

#define DEC_OFF   0
#define GEN_OFF   (B*UNITS)
#define COPY_OFF  (GEN_OFF + B*EXT)
#define PGEN_OFF  (COPY_OFF + B*EXT)

// ---------------- scratch ----------------
__device__ float g_xm[B * 3 * UNITS];
__device__ float g_hm[B * 3 * UNITS];
__device__ float g_q[B * UNITS];
__device__ float g_qw[B * UNITS];
__device__ float g_alpha[B * NSENT];
__device__ float g_xcat[B * 2 * UNITS];
__device__ float g_hraw[B * (UNITS/2)];
__device__ float g_hidden[B * (UNITS/2)];
__device__ float g_expsum[B];

// ============ small GEMM, two fused jobs ============
__global__ __launch_bounds__(256) void gemm_dual_kernel(
    const float* __restrict__ A0, int lda0, const float* __restrict__ B0, int ldb0,
    const float* __restrict__ bias0, float* __restrict__ C0, int ldc0, int K0, int nt0,
    const float* __restrict__ A1, int lda1, const float* __restrict__ B1, int ldb1,
    const float* __restrict__ bias1, float* __restrict__ C1, int ldc1, int K1)
{
    __shared__ float As[32][68];
    __shared__ float Bs[32][32];

    int bx = blockIdx.x;
    const float *A, *Bm, *bias; float* C; int lda, ldb, ldc, K, n0;
    if (bx < nt0) { A=A0; Bm=B0; bias=bias0; C=C0; lda=lda0; ldb=ldb0; ldc=ldc0; K=K0; n0=bx*32; }
    else          { A=A1; Bm=B1; bias=bias1; C=C1; lda=lda1; ldb=ldb1; ldc=ldc1; K=K1; n0=(bx-nt0)*32; }

    int tid = threadIdx.x;
    int tm = tid >> 4, tn = tid & 15;
    float acc[4][2] = {};

    for (int k0 = 0; k0 < K; k0 += 32) {
#pragma unroll
        for (int i = 0; i < 8; i++) {
            int idx = i * 256 + tid;
            int m  = idx >> 5;
            int kk = idx & 31;
            As[kk][m] = A[(size_t)m * lda + k0 + kk];
        }
        {
            int kk = tid >> 3;
            int c  = (tid & 7) * 4;
            *(float4*)&Bs[kk][c] = *(const float4*)(Bm + (size_t)(k0 + kk) * ldb + n0 + c);
        }
        __syncthreads();
#pragma unroll
        for (int k = 0; k < 32; k++) {
            float4 a = *(float4*)&As[k][tm * 4];
            float2 b = *(float2*)&Bs[k][tn * 2];
            acc[0][0] += a.x * b.x; acc[0][1] += a.x * b.y;
            acc[1][0] += a.y * b.x; acc[1][1] += a.y * b.y;
            acc[2][0] += a.z * b.x; acc[2][1] += a.z * b.y;
            acc[3][0] += a.w * b.x; acc[3][1] += a.w * b.y;
        }
        __syncthreads();
    }
#pragma unroll
    for (int jm = 0; jm < 4; jm++) {
        int m = tm * 4 + jm;
#pragma unroll
        for (int jn = 0; jn < 2; jn++) {
            int n = n0 + tn * 2 + jn;
            float v = acc[jm][jn];
            if (bias) v += bias[n];
            C[(size_t)m * ldc + n] = v;
        }
    }
}

// ============ split-K GEMM for weight_dec ============
__global__ __launch_bounds__(256) void gemm_splitk_kernel(
    const float* __restrict__ A, int lda, const float* __restrict__ Bm, int ldb,
    float* __restrict__ C, int ldc, int ksplit)
{
    __shared__ float As[32][68];
    __shared__ float Bs[32][32];
    int tid = threadIdx.x;
    int tm = tid >> 4, tn = tid & 15;
    int n0 = blockIdx.x * 32;
    int kbase = blockIdx.y * ksplit;

    float acc[4][2] = {};
    for (int kc = 0; kc < ksplit; kc += 32) {
        int k0 = kbase + kc;
#pragma unroll
        for (int i = 0; i < 8; i++) {
            int idx = i * 256 + tid;
            int m  = idx >> 5;
            int kk = idx & 31;
            As[kk][m] = A[(size_t)m * lda + k0 + kk];
        }
        {
            int kk = tid >> 3;
            int c  = (tid & 7) * 4;
            *(float4*)&Bs[kk][c] = *(const float4*)(Bm + (size_t)(k0 + kk) * ldb + n0 + c);
        }
        __syncthreads();
#pragma unroll
        for (int k = 0; k < 32; k++) {
            float4 a = *(float4*)&As[k][tm * 4];
            float2 b = *(float2*)&Bs[k][tn * 2];
            acc[0][0] += a.x * b.x; acc[0][1] += a.x * b.y;
            acc[1][0] += a.y * b.x; acc[1][1] += a.y * b.y;
            acc[2][0] += a.z * b.x; acc[2][1] += a.z * b.y;
            acc[3][0] += a.w * b.x; acc[3][1] += a.w * b.y;
        }
        __syncthreads();
    }
#pragma unroll
    for (int jm = 0; jm < 4; jm++) {
        int m = tm * 4 + jm;
#pragma unroll
        for (int jn = 0; jn < 2; jn++)
            atomicAdd(&C[(size_t)m * ldc + n0 + tn * 2 + jn], acc[jm][jn]);
    }
}

__global__ void tanh_kernel() {
    int i = blockIdx.x * blockDim.x + threadIdx.x;
    if (i < B * (UNITS/2)) g_hidden[i] = tanhf(g_hraw[i]);
}

// ============ fc GEMM: register-prefetch double-buffered pipeline, f32x2 FMA ============
// dynamic smem (floats): As2[2][32][132] | Bs[2][32][128] | red[64][17]
#define AS2_OFF 0
#define BS_OFF  8448
#define RED_OFF (8448 + 8192)
#define FC_SMEM ((8448 + 8192 + 1088) * 4)

__global__ __launch_bounds__(256) void fc_gemm_kernel(
    const float* __restrict__ Bm,      // fcW [256, 50000]
    const float* __restrict__ bias,
    float* __restrict__ out)
{
    extern __shared__ float sm[];
    float* As2 = sm + AS2_OFF;   // buf*4224 + k*132 + 2m{,+1}
    float* BsF = sm + BS_OFF;    // buf*4096 + k*128 + c
    float* red = sm + RED_OFF;   // m*17 + tc

    int tid = threadIdx.x;
    int tm = tid >> 4;      // 0..15
    int tc = tid & 15;      // 0..15
    int n0 = blockIdx.x * 128;

    unsigned long long acc[4][4];
#pragma unroll
    for (int i = 0; i < 4; i++)
#pragma unroll
        for (int j = 0; j < 4; j++) acc[i][j] = 0ULL;

    float  aregs[8];
    float4 bregs[4];

#define LDG_AB(c0) do { \
    _Pragma("unroll") \
    for (int i = 0; i < 8; i++) { \
        int idx = i * 256 + tid; int m = idx >> 5, kk = idx & 31; \
        aregs[i] = g_hidden[m * 256 + (c0) + kk]; \
    } \
    _Pragma("unroll") \
    for (int i = 0; i < 4; i++) { \
        int v = i * 256 + tid; int kk = v >> 5, cc = (v & 31) * 4; int n = n0 + cc; \
        bregs[i] = (n + 3 < VOCAB) \
            ? *(const float4*)(Bm + (size_t)((c0) + kk) * VOCAB + n) \
            : make_float4(0.f, 0.f, 0.f, 0.f); \
    } } while (0)

#define STS_AB(buf) do { \
    _Pragma("unroll") \
    for (int i = 0; i < 8; i++) { \
        int idx = i * 256 + tid; int m = idx >> 5, kk = idx & 31; \
        *(float2*)&As2[(buf) * 4224 + kk * 132 + 2 * m] = make_float2(aregs[i], aregs[i]); \
    } \
    _Pragma("unroll") \
    for (int i = 0; i < 4; i++) { \
        int v = i * 256 + tid; int kk = v >> 5, cc = (v & 31) * 4; \
        *(float4*)&BsF[(buf) * 4096 + kk * 128 + cc] = bregs[i]; \
    } } while (0)

    // prologue: chunk 0
    LDG_AB(0);
    STS_AB(0);
    __syncthreads();

#pragma unroll 1
    for (int c = 0; c < 8; c++) {
        int cur = c & 1, nxt = cur ^ 1;
        if (c < 7) LDG_AB((c + 1) * 32);   // prefetch into registers (overlaps compute)

        const float* Ab = As2 + cur * 4224 + tm * 8;
        const float* Bb = BsF + cur * 4096 + tc * 8;
#pragma unroll
        for (int k = 0; k < 32; k++) {
            ulonglong2 aA  = *(const ulonglong2*)(Ab + k * 132);
            ulonglong2 aB  = *(const ulonglong2*)(Ab + k * 132 + 4);
            ulonglong2 b01 = *(const ulonglong2*)(Bb + k * 128);
            ulonglong2 b23 = *(const ulonglong2*)(Bb + k * 128 + 4);
            unsigned long long ap0 = aA.x, ap1 = aA.y, ap2 = aB.x, ap3 = aB.y;
            unsigned long long bp0 = b01.x, bp1 = b01.y, bp2 = b23.x, bp3 = b23.y;
#define FMA2(d, a, b) asm volatile("fma.rn.f32x2 %0, %1, %2, %0;" : "+l"(d) : "l"(a), "l"(b))
            FMA2(acc[0][0], ap0, bp0); FMA2(acc[0][1], ap0, bp1);
            FMA2(acc[0][2], ap0, bp2); FMA2(acc[0][3], ap0, bp3);
            FMA2(acc[1][0], ap1, bp0); FMA2(acc[1][1], ap1, bp1);
            FMA2(acc[1][2], ap1, bp2); FMA2(acc[1][3], ap1, bp3);
            FMA2(acc[2][0], ap2, bp0); FMA2(acc[2][1], ap2, bp1);
            FMA2(acc[2][2], ap2, bp2); FMA2(acc[2][3], ap2, bp3);
            FMA2(acc[3][0], ap3, bp0); FMA2(acc[3][1], ap3, bp1);
            FMA2(acc[3][2], ap3, bp2); FMA2(acc[3][3], ap3, bp3);
#undef FMA2
        }
        if (c < 7) STS_AB(nxt);
        __syncthreads();
    }

    float rowsum[4] = {};
#pragma unroll
    for (int jm = 0; jm < 4; jm++) {
        int m = tm * 4 + jm;
#pragma unroll
        for (int jp = 0; jp < 4; jp++) {
            int n = n0 + tc * 8 + jp * 2;
            unsigned long long v = acc[jm][jp];
            if (n < VOCAB) {
                float e = __expf(__uint_as_float((unsigned)v) + bias[n]);
                out[GEN_OFF + (size_t)m * EXT + n] = e;
                rowsum[jm] += e;
            }
            if (n + 1 < VOCAB) {
                float e = __expf(__uint_as_float((unsigned)(v >> 32)) + bias[n + 1]);
                out[GEN_OFF + (size_t)m * EXT + n + 1] = e;
                rowsum[jm] += e;
            }
        }
    }
#pragma unroll
    for (int jm = 0; jm < 4; jm++) red[(tm * 4 + jm) * 17 + tc] = rowsum[jm];
    __syncthreads();
    if (tid < 64) {
        float s = 0.f;
#pragma unroll
        for (int i = 0; i < 16; i++) s += red[tid * 17 + i];
        atomicAdd(&g_expsum[tid], s);
    }
}

__global__ void normalize_kernel(float* __restrict__ out) {
    int idx = blockIdx.x * blockDim.x + threadIdx.x;
    if (idx >= B * EXT) return;
    int b = idx / EXT;
    int v = idx - b * EXT;
    float* p = out + GEN_OFF + idx;
    *p = (v < VOCAB) ? (*p) * (1.f / g_expsum[b]) : 0.f;
}

// ---------------- GRU gate ----------------
__global__ void gru_gate_kernel(const float* __restrict__ hprev, float* __restrict__ out) {
    int idx = blockIdx.x * blockDim.x + threadIdx.x;
    if (idx >= B * UNITS) return;
    int b = idx >> 9, u = idx & 511;
    const float* xm = g_xm + b * (3 * UNITS);
    const float* hm = g_hm + b * (3 * UNITS);
    float z  = 1.f / (1.f + __expf(-(xm[u] + hm[u])));
    float r  = 1.f / (1.f + __expf(-(xm[UNITS + u] + hm[UNITS + u])));
    float hc = tanhf(xm[2 * UNITS + u] + r * hm[2 * UNITS + u]);
    float h  = hprev[idx];
    float hn = z * h + (1.f - z) * hc;
    out[DEC_OFF + idx] = hn;
    g_xcat[b * (2 * UNITS) + UNITS + u] = hn;
}

// ---------------- sentence attention ----------------
__global__ __launch_bounds__(512) void attn_sent_kernel(const float* __restrict__ encS) {
    __shared__ float q_s[UNITS];
    __shared__ float sc_s[NSENT];
    __shared__ float alpha_s[NSENT];
    int b = blockIdx.x, tid = threadIdx.x;
    int warp = tid >> 5, lane = tid & 31;

    q_s[tid] = g_q[b * UNITS + tid];
    __syncthreads();
#pragma unroll
    for (int i = 0; i < 2; i++) {
        int s = warp * 2 + i;
        const float4* row = (const float4*)(encS + ((size_t)(b * NSENT + s)) * UNITS);
        const float4* qv  = (const float4*)q_s;
        float acc = 0.f;
#pragma unroll
        for (int t = 0; t < 4; t++) {
            float4 e = row[lane + t * 32], qq = qv[lane + t * 32];
            acc += e.x*qq.x + e.y*qq.y + e.z*qq.z + e.w*qq.w;
        }
#pragma unroll
        for (int o = 16; o > 0; o >>= 1) acc += __shfl_down_sync(0xffffffffu, acc, o);
        if (lane == 0) sc_s[s] = acc;
    }
    __syncthreads();
    if (warp == 0) {
        float x = sc_s[lane], m = x;
#pragma unroll
        for (int o = 16; o > 0; o >>= 1) m = fmaxf(m, __shfl_xor_sync(0xffffffffu, m, o));
        float e = __expf(x - m), s = e;
#pragma unroll
        for (int o = 16; o > 0; o >>= 1) s += __shfl_xor_sync(0xffffffffu, s, o);
        float a = e / s;
        alpha_s[lane] = a;
        g_alpha[b * NSENT + lane] = a;
    }
    __syncthreads();
    {
        float c = 0.f;
#pragma unroll
        for (int s = 0; s < NSENT; s++)
            c += alpha_s[s] * encS[((size_t)(b * NSENT + s)) * UNITS + tid];
        g_xcat[b * (2 * UNITS) + tid] = c;
    }
}

// ---------------- word attention + fused scatter ----------------
__global__ __launch_bounds__(256) void word_attn_scatter_kernel(
    const float* __restrict__ encW, const int* __restrict__ numeric,
    float* __restrict__ out)
{
    __shared__ float qw_s[UNITS];
    __shared__ float sc_s[NWORD];
    __shared__ float ms_s[2];
    int bid = blockIdx.x;
    int b = bid >> 5, s = bid & 31;
    int tid = threadIdx.x, warp = tid >> 5, lane = tid & 31;

    for (int u = tid; u < UNITS; u += 256) qw_s[u] = g_qw[b * UNITS + u];
    __syncthreads();
    const float* base = encW + ((size_t)(b * NSENT + s)) * NWORD * UNITS;
    for (int w = warp; w < NWORD; w += 8) {
        const float4* row = (const float4*)(base + (size_t)w * UNITS);
        const float4* qv  = (const float4*)qw_s;
        float acc = 0.f;
#pragma unroll
        for (int t = 0; t < 4; t++) {
            float4 e = row[lane + t * 32], qq = qv[lane + t * 32];
            acc += e.x*qq.x + e.y*qq.y + e.z*qq.z + e.w*qq.w;
        }
#pragma unroll
        for (int o = 16; o > 0; o >>= 1) acc += __shfl_down_sync(0xffffffffu, acc, o);
        if (lane == 0) sc_s[w] = acc;
    }
    __syncthreads();
    if (warp == 0) {
        float m = -1e30f;
        for (int i = lane; i < NWORD; i += 32) m = fmaxf(m, sc_s[i]);
#pragma unroll
        for (int o = 16; o > 0; o >>= 1) m = fmaxf(m, __shfl_xor_sync(0xffffffffu, m, o));
        float ssum = 0.f;
        for (int i = lane; i < NWORD; i += 32) ssum += __expf(sc_s[i] - m);
#pragma unroll
        for (int o = 16; o > 0; o >>= 1) ssum += __shfl_xor_sync(0xffffffffu, ssum, o);
        if (lane == 0) { ms_s[0] = m; ms_s[1] = ssum; }
    }
    __syncthreads();
    if (tid < NWORD) {
        float alpha = g_alpha[b * NSENT + s];
        float v = alpha * __expf(sc_s[tid] - ms_s[0]) / ms_s[1];
        int col = numeric[b * (NSENT * NWORD) + s * NWORD + tid];
        atomicAdd(&out[COPY_OFF + (size_t)b * EXT + col], v);
    }
}

__global__ __launch_bounds__(128) void pgen_kernel(
    const float* __restrict__ emb, const float* __restrict__ wc,
    const float* __restrict__ wh, const float* __restrict__ wi,
    float* __restrict__ out)
{
    __shared__ float red[128];
    int b = blockIdx.x, tid = threadIdx.x;
    const float* ctx = g_xcat + b * (2 * UNITS);
    const float* dec = ctx + UNITS;
    float acc = 0.f;
    for (int k = tid; k < UNITS; k += 128) {
        acc += ctx[k] * wc[k] + dec[k] * wh[k];
        if (k < EMB) acc += emb[b * EMB + k] * wi[k];
    }
    red[tid] = acc;
    __syncthreads();
    for (int o = 64; o > 0; o >>= 1) {
        if (tid < o) red[tid] += red[tid + o];
        __syncthreads();
    }
    if (tid == 0) out[PGEN_OFF + b] = 1.f / (1.f + __expf(-red[0]));
}

// ---------------- launch ----------------
extern "C" void kernel_launch(void* const* d_in, const int* in_sizes, int n_in,
                              void* d_out, int out_size)
{
    const float* emb   = (const float*)d_in[0];
    const float* hid   = (const float*)d_in[1];
    const float* encS  = (const float*)d_in[2];
    const float* encW  = (const float*)d_in[3];
    const int*   numr  = (const int*)d_in[4];
    int o = (in_sizes[5] == 1) ? 6 : 5;
    const float* gruWx = (const float*)d_in[o + 0];
    const float* gruWh = (const float*)d_in[o + 1];
    const float* grub  = (const float*)d_in[o + 2];
    const float* WatS  = (const float*)d_in[o + 3];
    const float* WatW  = (const float*)d_in[o + 4];
    const float* fcW   = (const float*)d_in[o + 5];
    const float* fcb   = (const float*)d_in[o + 6];
    const float* wctx  = (const float*)d_in[o + 7];
    const float* whid  = (const float*)d_in[o + 8];
    const float* wdec  = (const float*)d_in[o + 9];
    const float* winp  = (const float*)d_in[o + 10];

    float* out = (float*)d_out;

    float *xm, *hm, *q, *qw, *xcat, *hraw, *expsum;
    cudaGetSymbolAddress((void**)&xm, g_xm);
    cudaGetSymbolAddress((void**)&hm, g_hm);
    cudaGetSymbolAddress((void**)&q,  g_q);
    cudaGetSymbolAddress((void**)&qw, g_qw);
    cudaGetSymbolAddress((void**)&xcat, g_xcat);
    cudaGetSymbolAddress((void**)&hraw, g_hraw);
    cudaGetSymbolAddress((void**)&expsum, g_expsum);

    static cudaStream_t s1 = nullptr;
    static cudaEvent_t ev_fork = nullptr, ev_alpha = nullptr, ev_join = nullptr;
    if (!s1) {
        cudaStreamCreateWithFlags(&s1, cudaStreamNonBlocking);
        cudaEventCreateWithFlags(&ev_fork,  cudaEventDisableTiming);
        cudaEventCreateWithFlags(&ev_alpha, cudaEventDisableTiming);
        cudaEventCreateWithFlags(&ev_join,  cudaEventDisableTiming);
        cudaFuncSetAttribute(fc_gemm_kernel,
                             cudaFuncAttributeMaxDynamicSharedMemorySize, FC_SMEM);
    }

    // fork: side stream zeroes copy region while main chain starts
    cudaEventRecord(ev_fork, 0);
    cudaStreamWaitEvent(s1, ev_fork, 0);
    cudaMemsetAsync(out + COPY_OFF, 0, (size_t)B * EXT * sizeof(float), s1);

    cudaMemsetAsync(hraw, 0, B * (UNITS/2) * sizeof(float), 0);
    cudaMemsetAsync(expsum, 0, B * sizeof(float), 0);

    // GRU pre-activations (fused)
    gemm_dual_kernel<<<96, 256>>>(
        emb, EMB, gruWx, 3*UNITS, grub,           xm, 3*UNITS, EMB, 48,
        hid, UNITS, gruWh, 3*UNITS, grub+3*UNITS, hm, 3*UNITS, UNITS);
    gru_gate_kernel<<<(B*UNITS + 255)/256, 256>>>(hid, out);
    // attention queries (fused)
    gemm_dual_kernel<<<32, 256>>>(
        out + DEC_OFF, UNITS, WatS, UNITS, nullptr, q,  UNITS, UNITS, 16,
        out + DEC_OFF, UNITS, WatW, UNITS, nullptr, qw, UNITS, UNITS);
    attn_sent_kernel<<<B, 512>>>(encS);
    cudaEventRecord(ev_alpha, 0);

    // side stream: word attention + scatter + p_gen
    cudaStreamWaitEvent(s1, ev_alpha, 0);
    word_attn_scatter_kernel<<<B * NSENT, 256, 0, s1>>>(encW, numr, out);
    pgen_kernel<<<B, 128, 0, s1>>>(emb, wctx, whid, winp, out);
    cudaEventRecord(ev_join, s1);

    // main chain: hidden -> fc -> normalize
    gemm_splitk_kernel<<<dim3(8, 8), 256>>>(xcat, 2*UNITS, wdec, UNITS/2, hraw, UNITS/2, 128);
    tanh_kernel<<<(B*(UNITS/2) + 255)/256, 256>>>();
    fc_gemm_kernel<<<(VOCAB + 127)/128, 256, FC_SMEM>>>(fcW, fcb, out);
    normalize_kernel<<<(B*EXT + 255)/256, 256>>>(out);

    cudaStreamWaitEvent(0, ev_join, 0);
}

// round 7
// speedup vs baseline: 3.5535x; 1.5350x over previous
#include <cuda_runtime.h>
#include <math.h>
#include <stdint.h>

#define B 64
#define UNITS 512
#define EMB 256
#define NSENT 32
#define NWORD 50
#define VOCAB 50000
#define OOV 100
#define EXT (VOCAB + OOV)

#define DEC_OFF   0
#define GEN_OFF   (B*UNITS)
#define COPY_OFF  (GEN_OFF + B*EXT)
#define PGEN_OFF  (COPY_OFF + B*EXT)

// ---------------- scratch ----------------
__device__ float g_xm[B * 3 * UNITS];
__device__ float g_hm[B * 3 * UNITS];
__device__ float g_q[B * UNITS];
__device__ float g_qw[B * UNITS];
__device__ float g_alpha[B * NSENT];
__device__ float g_xcat[B * 2 * UNITS];
__device__ float g_hraw[B * (UNITS/2)];
__device__ float g_hidden[B * (UNITS/2)];
__device__ float g_expsum[B];

// ============ small GEMM, two fused jobs ============
__global__ __launch_bounds__(256) void gemm_dual_kernel(
    const float* __restrict__ A0, int lda0, const float* __restrict__ B0, int ldb0,
    const float* __restrict__ bias0, float* __restrict__ C0, int ldc0, int K0, int nt0,
    const float* __restrict__ A1, int lda1, const float* __restrict__ B1, int ldb1,
    const float* __restrict__ bias1, float* __restrict__ C1, int ldc1, int K1)
{
    __shared__ float As[32][68];
    __shared__ float Bs[32][32];

    int bx = blockIdx.x;
    const float *A, *Bm, *bias; float* C; int lda, ldb, ldc, K, n0;
    if (bx < nt0) { A=A0; Bm=B0; bias=bias0; C=C0; lda=lda0; ldb=ldb0; ldc=ldc0; K=K0; n0=bx*32; }
    else          { A=A1; Bm=B1; bias=bias1; C=C1; lda=lda1; ldb=ldb1; ldc=ldc1; K=K1; n0=(bx-nt0)*32; }

    int tid = threadIdx.x;
    int tm = tid >> 4, tn = tid & 15;
    float acc[4][2] = {};

    for (int k0 = 0; k0 < K; k0 += 32) {
#pragma unroll
        for (int i = 0; i < 8; i++) {
            int idx = i * 256 + tid;
            int m  = idx >> 5;
            int kk = idx & 31;
            As[kk][m] = A[(size_t)m * lda + k0 + kk];
        }
        {
            int kk = tid >> 3;
            int c  = (tid & 7) * 4;
            *(float4*)&Bs[kk][c] = *(const float4*)(Bm + (size_t)(k0 + kk) * ldb + n0 + c);
        }
        __syncthreads();
#pragma unroll
        for (int k = 0; k < 32; k++) {
            float4 a = *(float4*)&As[k][tm * 4];
            float2 b = *(float2*)&Bs[k][tn * 2];
            acc[0][0] += a.x * b.x; acc[0][1] += a.x * b.y;
            acc[1][0] += a.y * b.x; acc[1][1] += a.y * b.y;
            acc[2][0] += a.z * b.x; acc[2][1] += a.z * b.y;
            acc[3][0] += a.w * b.x; acc[3][1] += a.w * b.y;
        }
        __syncthreads();
    }
#pragma unroll
    for (int jm = 0; jm < 4; jm++) {
        int m = tm * 4 + jm;
#pragma unroll
        for (int jn = 0; jn < 2; jn++) {
            int n = n0 + tn * 2 + jn;
            float v = acc[jm][jn];
            if (bias) v += bias[n];
            C[(size_t)m * ldc + n] = v;
        }
    }
}

// ============ split-K GEMM for weight_dec ============
__global__ __launch_bounds__(256) void gemm_splitk_kernel(
    const float* __restrict__ A, int lda, const float* __restrict__ Bm, int ldb,
    float* __restrict__ C, int ldc, int ksplit)
{
    __shared__ float As[32][68];
    __shared__ float Bs[32][32];
    int tid = threadIdx.x;
    int tm = tid >> 4, tn = tid & 15;
    int n0 = blockIdx.x * 32;
    int kbase = blockIdx.y * ksplit;

    float acc[4][2] = {};
    for (int kc = 0; kc < ksplit; kc += 32) {
        int k0 = kbase + kc;
#pragma unroll
        for (int i = 0; i < 8; i++) {
            int idx = i * 256 + tid;
            int m  = idx >> 5;
            int kk = idx & 31;
            As[kk][m] = A[(size_t)m * lda + k0 + kk];
        }
        {
            int kk = tid >> 3;
            int c  = (tid & 7) * 4;
            *(float4*)&Bs[kk][c] = *(const float4*)(Bm + (size_t)(k0 + kk) * ldb + n0 + c);
        }
        __syncthreads();
#pragma unroll
        for (int k = 0; k < 32; k++) {
            float4 a = *(float4*)&As[k][tm * 4];
            float2 b = *(float2*)&Bs[k][tn * 2];
            acc[0][0] += a.x * b.x; acc[0][1] += a.x * b.y;
            acc[1][0] += a.y * b.x; acc[1][1] += a.y * b.y;
            acc[2][0] += a.z * b.x; acc[2][1] += a.z * b.y;
            acc[3][0] += a.w * b.x; acc[3][1] += a.w * b.y;
        }
        __syncthreads();
    }
#pragma unroll
    for (int jm = 0; jm < 4; jm++) {
        int m = tm * 4 + jm;
#pragma unroll
        for (int jn = 0; jn < 2; jn++)
            atomicAdd(&C[(size_t)m * ldc + n0 + tn * 2 + jn], acc[jm][jn]);
    }
}

__global__ void tanh_kernel() {
    int i = blockIdx.x * blockDim.x + threadIdx.x;
    if (i < B * (UNITS/2)) g_hidden[i] = tanhf(g_hraw[i]);
}

// ============ fc GEMM v3: tf32 mma.sync m16n8k8, exp epilogue + row sums ============
// dynamic smem (floats): A_tf32[64][260] | B_tf32[2][32][136] | red[64]
#define FC_A_FLOATS  (64 * 260)                  // 16640
#define FC_B_FLOATS  (2 * 32 * 136)              // 8704
#define FC_SMEM      ((FC_A_FLOATS + FC_B_FLOATS + 64) * 4)

__device__ __forceinline__ uint32_t f2tf32(float f) {
    uint32_t t;
    asm("cvt.rna.tf32.f32 %0, %1;" : "=r"(t) : "f"(f));
    return t;
}

__global__ __launch_bounds__(256) void fc_gemm_kernel(
    const float* __restrict__ Bm,      // fcW [256, 50000]
    const float* __restrict__ bias,
    float* __restrict__ out)
{
    extern __shared__ float sm[];
    uint32_t* As  = (uint32_t*)sm;                    // [64][260] tf32
    uint32_t* Bs  = (uint32_t*)(sm + FC_A_FLOATS);    // [2][32][136] tf32
    float*    red = sm + FC_A_FLOATS + FC_B_FLOATS;   // [64]

    int tid  = threadIdx.x;
    int lane = tid & 31;
    int w    = tid >> 5;            // 0..7
    int m0   = (w & 3) * 16;        // warp m-tile
    int n0w  = (w >> 2) * 64;       // warp n-half within block tile
    int n0   = blockIdx.x * 128;
    int r    = lane >> 2;           // 0..7
    int cq   = lane & 3;            // 0..3

    if (tid < 64) red[tid] = 0.f;

    // stage A (g_hidden, 64x256) once, tf32-converted; coalesced LDG, linear STS
#pragma unroll 4
    for (int i = 0; i < 64; i++) {
        int idx = i * 256 + tid;
        int m = idx >> 8, k = idx & 255;
        As[m * 260 + k] = f2tf32(g_hidden[idx]);
    }

    float c[8][4];
#pragma unroll
    for (int i = 0; i < 8; i++)
#pragma unroll
        for (int j = 0; j < 4; j++) c[i][j] = 0.f;

    float4 bregs[4];

#define LDG_B(c0) do { \
    _Pragma("unroll") \
    for (int i = 0; i < 4; i++) { \
        int v = i * 256 + tid; int kk = v >> 5, cc = (v & 31) * 4; int n = n0 + cc; \
        bregs[i] = (n + 3 < VOCAB) \
            ? *(const float4*)(Bm + (size_t)((c0) + kk) * VOCAB + n) \
            : make_float4(0.f, 0.f, 0.f, 0.f); \
    } } while (0)

#define STS_B(buf) do { \
    _Pragma("unroll") \
    for (int i = 0; i < 4; i++) { \
        int v = i * 256 + tid; int kk = v >> 5, cc = (v & 31) * 4; \
        uint32_t* p = Bs + (buf) * 4352 + kk * 136 + cc; \
        p[0] = f2tf32(bregs[i].x); p[1] = f2tf32(bregs[i].y); \
        p[2] = f2tf32(bregs[i].z); p[3] = f2tf32(bregs[i].w); \
    } } while (0)

    // prologue
    LDG_B(0);
    STS_B(0);
    __syncthreads();

#pragma unroll 1
    for (int ch = 0; ch < 8; ch++) {
        int cur = ch & 1, nxt = cur ^ 1;
        if (ch < 7) LDG_B((ch + 1) * 32);

        const uint32_t* Bb = Bs + cur * 4352;
#pragma unroll
        for (int k8 = 0; k8 < 4; k8++) {
            int gk = ch * 32 + k8 * 8;
            uint32_t a0 = As[(m0 + r)     * 260 + gk + cq];
            uint32_t a1 = As[(m0 + r + 8) * 260 + gk + cq];
            uint32_t a2 = As[(m0 + r)     * 260 + gk + cq + 4];
            uint32_t a3 = As[(m0 + r + 8) * 260 + gk + cq + 4];
            const uint32_t* brow0 = Bb + (k8 * 8 + cq) * 136;
            const uint32_t* brow1 = brow0 + 4 * 136;
#pragma unroll
            for (int nt = 0; nt < 8; nt++) {
                uint32_t b0 = brow0[n0w + nt * 8 + r];
                uint32_t b1 = brow1[n0w + nt * 8 + r];
                asm volatile(
                    "mma.sync.aligned.m16n8k8.row.col.f32.tf32.tf32.f32 "
                    "{%0,%1,%2,%3}, {%4,%5,%6,%7}, {%8,%9}, {%0,%1,%2,%3};"
                    : "+f"(c[nt][0]), "+f"(c[nt][1]), "+f"(c[nt][2]), "+f"(c[nt][3])
                    : "r"(a0), "r"(a1), "r"(a2), "r"(a3), "r"(b0), "r"(b1));
            }
        }
        if (ch < 7) STS_B(nxt);
        __syncthreads();
    }

    // epilogue: exp + write + per-row sums
    int row_lo = m0 + r;
    int row_hi = row_lo + 8;
    float sum_lo = 0.f, sum_hi = 0.f;
#pragma unroll
    for (int nt = 0; nt < 8; nt++) {
        int ncol = n0 + n0w + nt * 8 + cq * 2;
        if (ncol + 1 < VOCAB) {
            float e0 = __expf(c[nt][0] + bias[ncol]);
            float e1 = __expf(c[nt][1] + bias[ncol + 1]);
            float e2 = __expf(c[nt][2] + bias[ncol]);
            float e3 = __expf(c[nt][3] + bias[ncol + 1]);
            *(float2*)&out[GEN_OFF + (size_t)row_lo * EXT + ncol] = make_float2(e0, e1);
            *(float2*)&out[GEN_OFF + (size_t)row_hi * EXT + ncol] = make_float2(e2, e3);
            sum_lo += e0 + e1;
            sum_hi += e2 + e3;
        } else if (ncol < VOCAB) {
            float e0 = __expf(c[nt][0] + bias[ncol]);
            float e2 = __expf(c[nt][2] + bias[ncol]);
            out[GEN_OFF + (size_t)row_lo * EXT + ncol] = e0;
            out[GEN_OFF + (size_t)row_hi * EXT + ncol] = e2;
            sum_lo += e0;
            sum_hi += e2;
        }
    }
    atomicAdd(&red[row_lo], sum_lo);
    atomicAdd(&red[row_hi], sum_hi);
    __syncthreads();
    if (tid < 64) atomicAdd(&g_expsum[tid], red[tid]);
}

__global__ void normalize_kernel(float* __restrict__ out) {
    int idx = blockIdx.x * blockDim.x + threadIdx.x;
    if (idx >= B * EXT) return;
    int b = idx / EXT;
    int v = idx - b * EXT;
    float* p = out + GEN_OFF + idx;
    *p = (v < VOCAB) ? (*p) * (1.f / g_expsum[b]) : 0.f;
}

// ---------------- GRU gate ----------------
__global__ void gru_gate_kernel(const float* __restrict__ hprev, float* __restrict__ out) {
    int idx = blockIdx.x * blockDim.x + threadIdx.x;
    if (idx >= B * UNITS) return;
    int b = idx >> 9, u = idx & 511;
    const float* xm = g_xm + b * (3 * UNITS);
    const float* hm = g_hm + b * (3 * UNITS);
    float z  = 1.f / (1.f + __expf(-(xm[u] + hm[u])));
    float r  = 1.f / (1.f + __expf(-(xm[UNITS + u] + hm[UNITS + u])));
    float hc = tanhf(xm[2 * UNITS + u] + r * hm[2 * UNITS + u]);
    float h  = hprev[idx];
    float hn = z * h + (1.f - z) * hc;
    out[DEC_OFF + idx] = hn;
    g_xcat[b * (2 * UNITS) + UNITS + u] = hn;
}

// ---------------- sentence attention ----------------
__global__ __launch_bounds__(512) void attn_sent_kernel(const float* __restrict__ encS) {
    __shared__ float q_s[UNITS];
    __shared__ float sc_s[NSENT];
    __shared__ float alpha_s[NSENT];
    int b = blockIdx.x, tid = threadIdx.x;
    int warp = tid >> 5, lane = tid & 31;

    q_s[tid] = g_q[b * UNITS + tid];
    __syncthreads();
#pragma unroll
    for (int i = 0; i < 2; i++) {
        int s = warp * 2 + i;
        const float4* row = (const float4*)(encS + ((size_t)(b * NSENT + s)) * UNITS);
        const float4* qv  = (const float4*)q_s;
        float acc = 0.f;
#pragma unroll
        for (int t = 0; t < 4; t++) {
            float4 e = row[lane + t * 32], qq = qv[lane + t * 32];
            acc += e.x*qq.x + e.y*qq.y + e.z*qq.z + e.w*qq.w;
        }
#pragma unroll
        for (int o = 16; o > 0; o >>= 1) acc += __shfl_down_sync(0xffffffffu, acc, o);
        if (lane == 0) sc_s[s] = acc;
    }
    __syncthreads();
    if (warp == 0) {
        float x = sc_s[lane], m = x;
#pragma unroll
        for (int o = 16; o > 0; o >>= 1) m = fmaxf(m, __shfl_xor_sync(0xffffffffu, m, o));
        float e = __expf(x - m), s = e;
#pragma unroll
        for (int o = 16; o > 0; o >>= 1) s += __shfl_xor_sync(0xffffffffu, s, o);
        float a = e / s;
        alpha_s[lane] = a;
        g_alpha[b * NSENT + lane] = a;
    }
    __syncthreads();
    {
        float c = 0.f;
#pragma unroll
        for (int s = 0; s < NSENT; s++)
            c += alpha_s[s] * encS[((size_t)(b * NSENT + s)) * UNITS + tid];
        g_xcat[b * (2 * UNITS) + tid] = c;
    }
}

// ---------------- word attention + fused scatter ----------------
__global__ __launch_bounds__(256) void word_attn_scatter_kernel(
    const float* __restrict__ encW, const int* __restrict__ numeric,
    float* __restrict__ out)
{
    __shared__ float qw_s[UNITS];
    __shared__ float sc_s[NWORD];
    __shared__ float ms_s[2];
    int bid = blockIdx.x;
    int b = bid >> 5, s = bid & 31;
    int tid = threadIdx.x, warp = tid >> 5, lane = tid & 31;

    for (int u = tid; u < UNITS; u += 256) qw_s[u] = g_qw[b * UNITS + u];
    __syncthreads();
    const float* base = encW + ((size_t)(b * NSENT + s)) * NWORD * UNITS;
    for (int w = warp; w < NWORD; w += 8) {
        const float4* row = (const float4*)(base + (size_t)w * UNITS);
        const float4* qv  = (const float4*)qw_s;
        float acc = 0.f;
#pragma unroll
        for (int t = 0; t < 4; t++) {
            float4 e = row[lane + t * 32], qq = qv[lane + t * 32];
            acc += e.x*qq.x + e.y*qq.y + e.z*qq.z + e.w*qq.w;
        }
#pragma unroll
        for (int o = 16; o > 0; o >>= 1) acc += __shfl_down_sync(0xffffffffu, acc, o);
        if (lane == 0) sc_s[w] = acc;
    }
    __syncthreads();
    if (warp == 0) {
        float m = -1e30f;
        for (int i = lane; i < NWORD; i += 32) m = fmaxf(m, sc_s[i]);
#pragma unroll
        for (int o = 16; o > 0; o >>= 1) m = fmaxf(m, __shfl_xor_sync(0xffffffffu, m, o));
        float ssum = 0.f;
        for (int i = lane; i < NWORD; i += 32) ssum += __expf(sc_s[i] - m);
#pragma unroll
        for (int o = 16; o > 0; o >>= 1) ssum += __shfl_xor_sync(0xffffffffu, ssum, o);
        if (lane == 0) { ms_s[0] = m; ms_s[1] = ssum; }
    }
    __syncthreads();
    if (tid < NWORD) {
        float alpha = g_alpha[b * NSENT + s];
        float v = alpha * __expf(sc_s[tid] - ms_s[0]) / ms_s[1];
        int col = numeric[b * (NSENT * NWORD) + s * NWORD + tid];
        atomicAdd(&out[COPY_OFF + (size_t)b * EXT + col], v);
    }
}

__global__ __launch_bounds__(128) void pgen_kernel(
    const float* __restrict__ emb, const float* __restrict__ wc,
    const float* __restrict__ wh, const float* __restrict__ wi,
    float* __restrict__ out)
{
    __shared__ float red[128];
    int b = blockIdx.x, tid = threadIdx.x;
    const float* ctx = g_xcat + b * (2 * UNITS);
    const float* dec = ctx + UNITS;
    float acc = 0.f;
    for (int k = tid; k < UNITS; k += 128) {
        acc += ctx[k] * wc[k] + dec[k] * wh[k];
        if (k < EMB) acc += emb[b * EMB + k] * wi[k];
    }
    red[tid] = acc;
    __syncthreads();
    for (int o = 64; o > 0; o >>= 1) {
        if (tid < o) red[tid] += red[tid + o];
        __syncthreads();
    }
    if (tid == 0) out[PGEN_OFF + b] = 1.f / (1.f + __expf(-red[0]));
}

// ---------------- launch ----------------
extern "C" void kernel_launch(void* const* d_in, const int* in_sizes, int n_in,
                              void* d_out, int out_size)
{
    const float* emb   = (const float*)d_in[0];
    const float* hid   = (const float*)d_in[1];
    const float* encS  = (const float*)d_in[2];
    const float* encW  = (const float*)d_in[3];
    const int*   numr  = (const int*)d_in[4];
    int o = (in_sizes[5] == 1) ? 6 : 5;
    const float* gruWx = (const float*)d_in[o + 0];
    const float* gruWh = (const float*)d_in[o + 1];
    const float* grub  = (const float*)d_in[o + 2];
    const float* WatS  = (const float*)d_in[o + 3];
    const float* WatW  = (const float*)d_in[o + 4];
    const float* fcW   = (const float*)d_in[o + 5];
    const float* fcb   = (const float*)d_in[o + 6];
    const float* wctx  = (const float*)d_in[o + 7];
    const float* whid  = (const float*)d_in[o + 8];
    const float* wdec  = (const float*)d_in[o + 9];
    const float* winp  = (const float*)d_in[o + 10];

    float* out = (float*)d_out;

    float *xm, *hm, *q, *qw, *xcat, *hraw, *expsum;
    cudaGetSymbolAddress((void**)&xm, g_xm);
    cudaGetSymbolAddress((void**)&hm, g_hm);
    cudaGetSymbolAddress((void**)&q,  g_q);
    cudaGetSymbolAddress((void**)&qw, g_qw);
    cudaGetSymbolAddress((void**)&xcat, g_xcat);
    cudaGetSymbolAddress((void**)&hraw, g_hraw);
    cudaGetSymbolAddress((void**)&expsum, g_expsum);

    static cudaStream_t s1 = nullptr;
    static cudaEvent_t ev_fork = nullptr, ev_alpha = nullptr, ev_join = nullptr;
    if (!s1) {
        cudaStreamCreateWithFlags(&s1, cudaStreamNonBlocking);
        cudaEventCreateWithFlags(&ev_fork,  cudaEventDisableTiming);
        cudaEventCreateWithFlags(&ev_alpha, cudaEventDisableTiming);
        cudaEventCreateWithFlags(&ev_join,  cudaEventDisableTiming);
        cudaFuncSetAttribute(fc_gemm_kernel,
                             cudaFuncAttributeMaxDynamicSharedMemorySize, FC_SMEM);
    }

    // fork: side stream zeroes copy region while main chain starts
    cudaEventRecord(ev_fork, 0);
    cudaStreamWaitEvent(s1, ev_fork, 0);
    cudaMemsetAsync(out + COPY_OFF, 0, (size_t)B * EXT * sizeof(float), s1);

    cudaMemsetAsync(hraw, 0, B * (UNITS/2) * sizeof(float), 0);
    cudaMemsetAsync(expsum, 0, B * sizeof(float), 0);

    // GRU pre-activations (fused)
    gemm_dual_kernel<<<96, 256>>>(
        emb, EMB, gruWx, 3*UNITS, grub,           xm, 3*UNITS, EMB, 48,
        hid, UNITS, gruWh, 3*UNITS, grub+3*UNITS, hm, 3*UNITS, UNITS);
    gru_gate_kernel<<<(B*UNITS + 255)/256, 256>>>(hid, out);
    // attention queries (fused)
    gemm_dual_kernel<<<32, 256>>>(
        out + DEC_OFF, UNITS, WatS, UNITS, nullptr, q,  UNITS, UNITS, 16,
        out + DEC_OFF, UNITS, WatW, UNITS, nullptr, qw, UNITS, UNITS);
    attn_sent_kernel<<<B, 512>>>(encS);
    cudaEventRecord(ev_alpha, 0);

    // side stream: word attention + scatter + p_gen
    cudaStreamWaitEvent(s1, ev_alpha, 0);
    word_attn_scatter_kernel<<<B * NSENT, 256, 0, s1>>>(encW, numr, out);
    pgen_kernel<<<B, 128, 0, s1>>>(emb, wctx, whid, winp, out);
    cudaEventRecord(ev_join, s1);

    // main chain: hidden -> fc -> normalize
    gemm_splitk_kernel<<<dim3(8, 8), 256>>>(xcat, 2*UNITS, wdec, UNITS/2, hraw, UNITS/2, 128);
    tanh_kernel<<<(B*(UNITS/2) + 255)/256, 256>>>();
    fc_gemm_kernel<<<(VOCAB + 127)/128, 256, FC_SMEM>>>(fcW, fcb, out);
    normalize_kernel<<<(B*EXT + 255)/256, 256>>>(out);

    cudaStreamWaitEvent(0, ev_join, 0);
}